// round 10
// baseline (speedup 1.0000x reference)
#include <cuda_runtime.h>
#include <cuda_bf16.h>
#include <cstdint>

#define BH    32
#define LSEQ  4096
#define DDIM  64
#define NBLK  64
#define TK    6
#define STR   68          // fp32 epilogue stride
#define QSTR  80          // quad-layout row stride in u32
#define ATT_SCALE 0.125f

typedef unsigned long long ull;
typedef unsigned int u32;

// ---------------- f32x2 packed helpers ----------------
__device__ __forceinline__ ull fma2(ull a, ull b, ull c) {
    ull d; asm("fma.rn.f32x2 %0,%1,%2,%3;" : "=l"(d) : "l"(a), "l"(b), "l"(c)); return d;
}
__device__ __forceinline__ ull splat2(float a) {
    ull r; asm("mov.b64 %0,{%1,%1};" : "=l"(r) : "f"(a)); return r;
}
__device__ __forceinline__ void upk2(ull x, float& a, float& b) {
    asm("mov.b64 {%0,%1},%2;" : "=f"(a), "=f"(b) : "l"(x));
}

// ---------------- bf16 split helpers ----------------
__device__ __forceinline__ u32 packbf(float e, float o) {
    u32 r; asm("cvt.rn.bf16x2.f32 %0,%1,%2;" : "=r"(r) : "f"(o), "f"(e)); return r;
}
__device__ __forceinline__ float lo_f(u32 u) { return __uint_as_float(u << 16); }
__device__ __forceinline__ float hi_f(u32 u) { return __uint_as_float(u & 0xffff0000u); }
__device__ __forceinline__ void split2(float f0, float f1, u32& h, u32& l) {
    h = packbf(f0, f1);
    l = packbf(f0 - lo_f(h), f1 - hi_f(h));
}

// ---------------- mma.sync m16n8k16 bf16 ----------------
__device__ __forceinline__ void mma16816(float* c, const u32* a, const u32* b) {
    asm("mma.sync.aligned.m16n8k16.row.col.f32.bf16.bf16.f32 "
        "{%0,%1,%2,%3},{%4,%5,%6,%7},{%8,%9},{%0,%1,%2,%3};"
        : "+f"(c[0]), "+f"(c[1]), "+f"(c[2]), "+f"(c[3])
        : "r"(a[0]), "r"(a[1]), "r"(a[2]), "r"(a[3]), "r"(b[0]), "r"(b[1]));
}

// ---------------- device scratch ----------------
__device__ float g_qmean[BH * NBLK * DDIM];
__device__ float g_kmean[BH * NBLK * DDIM];
__device__ int   g_lut[BH * NBLK * TK];
__device__ float g_kv[(size_t)BH * NBLK * DDIM * DDIM];
__device__ float g_z[BH * NBLK * DDIM];
__device__ float g_kvtot[BH * DDIM * DDIM];
__device__ float g_ztot[BH * DDIM];

// ================= K1: fused mean-pool + per-block kv/z (R9 broadcast mapping) =================
__global__ void __launch_bounds__(256) kvpool_kernel(
    const float* __restrict__ q, const float* __restrict__ k, const float* __restrict__ v)
{
    __shared__ __align__(16) float Ks[64 * 65];
    __shared__ __align__(16) float Vs[64 * STR];
    const int tid = threadIdx.x;
    const size_t base = (size_t)blockIdx.x * 4096;
    for (int i = tid; i < 4096; i += 256)
        Ks[(i >> 6) * 65 + (i & 63)] = k[base + i];
    for (int i4 = tid; i4 < 1024; i4 += 256) {
        int c = i4 >> 4, e = (i4 & 15) * 4;
        *(float4*)&Vs[c * STR + e] = *(const float4*)&v[base + c * 64 + e];
    }
    __syncthreads();
    if (tid < 64) {
        float s = 0.f;
#pragma unroll
        for (int m = 0; m < 64; m++) s += Ks[m * 65 + tid];
        g_kmean[blockIdx.x * 64 + tid] = s * (1.f / 64.f);
    } else if (tid < 128) {
        const int d = tid - 64;
        const float* p = q + base + d;
        float s = 0.f;
#pragma unroll
        for (int m = 0; m < 64; m++) s += p[m * 64];
        g_qmean[blockIdx.x * 64 + d] = s * (1.f / 64.f);
    }
    __syncthreads();
    if (tid < 64) {                       // phi(k): row softmax
        float* row = &Ks[tid * 65];
        float mx = -1e30f;
#pragma unroll
        for (int i = 0; i < 64; i++) mx = fmaxf(mx, row[i]);
        float s = 0.f;
#pragma unroll
        for (int i = 0; i < 64; i++) { float e = __expf(row[i] - mx); row[i] = e; s += e; }
        float inv = 1.f / s;
#pragma unroll
        for (int i = 0; i < 64; i++) row[i] *= inv;
    }
    __syncthreads();
    if (tid < 64) {
        float s = 0.f;
#pragma unroll
        for (int m = 0; m < 64; m++) s += Ks[m * 65 + tid];
        g_z[(size_t)blockIdx.x * 64 + tid] = s;
    }
    const int d = tid & 63;               // per-lane distinct within warp
    const int e0 = (tid >> 6) * 16;       // warp-uniform -> broadcast Vs reads
    ull acc[8];
#pragma unroll
    for (int i = 0; i < 8; i++) acc[i] = 0ull;
#pragma unroll 4
    for (int m = 0; m < 64; m++) {
        ull cc = splat2(Ks[m * 65 + d]);
        const ull* vp = (const ull*)&Vs[m * STR + e0];
#pragma unroll
        for (int t = 0; t < 8; t++) acc[t] = fma2(cc, vp[t], acc[t]);
    }
    float* op = &g_kv[(size_t)blockIdx.x * 4096 + d * 64 + e0];
#pragma unroll
    for (int u = 0; u < 4; u++) {
        float4 f;
        upk2(acc[2 * u], f.x, f.y);
        upk2(acc[2 * u + 1], f.z, f.w);
        *(float4*)&op[4 * u] = f;
    }
}

// ================= K2: block scores + top-6 (warp argmax) =================
__global__ void topk_kernel() {
    __shared__ float km[64 * 65];
    __shared__ float qv[64];
    __shared__ float sc[64];
    const int bh = blockIdx.x >> 6, qi = blockIdx.x & 63;
    const int tid = threadIdx.x;
    for (int i = tid; i < 4096; i += 64) km[(i >> 6) * 65 + (i & 63)] = g_kmean[bh * 4096 + i];
    qv[tid] = g_qmean[bh * 4096 + qi * 64 + tid];
    __syncthreads();
    float s = 0.f;
#pragma unroll
    for (int d = 0; d < 64; d++) s += qv[d] * km[tid * 65 + d];
    sc[tid] = s;
    __syncthreads();
    if (tid < 32) {
        float s0 = sc[tid], s1 = sc[tid + 32];
        int* lp = &g_lut[(bh * 64 + qi) * TK];
#pragma unroll
        for (int t = 0; t < TK; t++) {
            float m = (s1 > s0) ? s1 : s0;
            int idx = (s1 > s0) ? (tid + 32) : tid;
#pragma unroll
            for (int off = 16; off; off >>= 1) {
                float om = __shfl_xor_sync(0xffffffffu, m, off);
                int oi = __shfl_xor_sync(0xffffffffu, idx, off);
                if (om > m || (om == m && oi < idx)) { m = om; idx = oi; }
            }
            if (tid == 0) lp[t] = idx;
            if (idx == tid) s0 = -1e38f;
            if (idx == tid + 32) s1 = -1e38f;
        }
    }
}

// ================= K3: totals over key blocks =================
__global__ void total_kernel() {
    const int bh = blockIdx.x;
    const int o = blockIdx.y * 256 + threadIdx.x;
    const float* p = &g_kv[(size_t)bh * NBLK * 4096 + o];
    float s = 0.f;
#pragma unroll 8
    for (int b = 0; b < NBLK; b++) s += p[(size_t)b * 4096];
    g_kvtot[bh * 4096 + o] = s;
    if (blockIdx.y == 0 && threadIdx.x < 64) {
        float z = 0.f;
#pragma unroll
        for (int b = 0; b < NBLK; b++) z += g_z[((size_t)bh * NBLK + b) * 64 + threadIdx.x];
        g_ztot[bh * 64 + threadIdx.x] = z;
    }
}

// ================= K4: fused sparse attention + linear + proj =================
// R7 control flow (single buffer, sync-load-sync-mma) + R8 quad smem layout:
// uint4 (h_p, l_p, h_{p+4}, l_{p+4}) per 16B -> 1 LDS.128 per B-fragment triple,
// 2 LDS.128 per A-fragment octet, STS.128 converts. No cross-mma register state.
__global__ void __launch_bounds__(128) attn_kernel(
    const float* __restrict__ q, const float* __restrict__ k, const float* __restrict__ v,
    const float* __restrict__ Wl, const float* __restrict__ bl, float* __restrict__ out)
{
    extern __shared__ __align__(16) unsigned char smraw[];
    u32* Qt = (u32*)smraw;                       // quad layout (persistent)
    unsigned char* U = (unsigned char*)(Qt + 64 * QSTR);   // union
    u32* Kq = (u32*)U;                           // quad layout [key][pair d]
    u32* Vq = Kq + 64 * QSTR;                    // quad layout [e][pair key]
    float* OS   = (float*)U;                     // epilogue overlay
    float* PhiT = OS   + 64 * STR;
    float* KVns = PhiT + 64 * STR;
    float* OlS  = KVns + 64 * STR;
    float* Wlt  = OlS  + 64 * STR;
    float* zns  = Wlt  + 64 * STR;
    __shared__ int lut[8];

    const int tid  = threadIdx.x;
    const int lane = tid & 31;
    const int R    = (tid >> 5) * 16;
    const int g    = lane >> 2, t = lane & 3;
    const int tx4  = (t ^ ((g >> 1) & 3)) * 4;   // unswizzled quad offset for frag loads
    const int bh = blockIdx.x >> 6, qi = blockIdx.x & 63;
    const size_t qbase = ((size_t)bh * LSEQ + qi * 64) * DDIM;

    if (tid < TK) lut[tid] = g_lut[(bh * 64 + qi) * TK + tid];
    // Q convert into quad layout
#pragma unroll
    for (int it = 0; it < 8; it++) {
        int id = tid + 128 * it;
        int c = id >> 4, oct = (id >> 2) & 3, qq = id & 3;
        const float* p = q + qbase + c * 64 + oct * 16 + 2 * qq;
        float2 A = *(const float2*)p;
        float2 B = *(const float2*)(p + 8);
        u32 h0, l0, h1, l1;
        split2(A.x, A.y, h0, l0);
        split2(B.x, B.y, h1, l1);
        int qp = qq ^ ((c >> 1) & 3);
        *(uint4*)&Qt[c * QSTR + oct * 16 + qp * 4] = make_uint4(h0, l0, h1, l1);
    }

    float O[8][4];
#pragma unroll
    for (int i = 0; i < 8; i++) { O[i][0] = O[i][1] = O[i][2] = O[i][3] = 0.f; }
    float rs0 = 0.f, rs1 = 0.f;

    for (int j = 0; j < TK; j++) {
        __syncthreads();
        const size_t kbase = ((size_t)bh * LSEQ + lut[j] * 64) * DDIM;
        // K convert (quad)
#pragma unroll
        for (int it = 0; it < 8; it++) {
            int id = tid + 128 * it;
            int c = id >> 4, oct = (id >> 2) & 3, qq = id & 3;
            const float* p = k + kbase + c * 64 + oct * 16 + 2 * qq;
            float2 A = *(const float2*)p;
            float2 B = *(const float2*)(p + 8);
            u32 h0, l0, h1, l1;
            split2(A.x, A.y, h0, l0);
            split2(B.x, B.y, h1, l1);
            int qp = qq ^ ((c >> 1) & 3);
            *(uint4*)&Kq[c * QSTR + oct * 16 + qp * 4] = make_uint4(h0, l0, h1, l1);
        }
        // V transpose convert (quad)
#pragma unroll
        for (int it = 0; it < 8; it++) {
            int id = tid + 128 * it;
            int e = id & 63, slot = id >> 6;
            int oct = slot >> 2, qq = slot & 3;
            int m0 = oct * 16 + 2 * qq;
            const float* vp = v + kbase + e;
            float a0 = vp[m0 * 64],       a1 = vp[(m0 + 1) * 64];
            float a2 = vp[(m0 + 8) * 64], a3 = vp[(m0 + 9) * 64];
            u32 h0, l0, h1, l1;
            split2(a0, a1, h0, l0);
            split2(a2, a3, h1, l1);
            int qp = qq ^ ((e >> 1) & 3);
            *(uint4*)&Vq[e * QSTR + oct * 16 + qp * 4] = make_uint4(h0, l0, h1, l1);
        }
        __syncthreads();

        // ---- S = Q K^T ----
        float S[8][4];
#pragma unroll
        for (int i = 0; i < 8; i++) { S[i][0] = S[i][1] = S[i][2] = S[i][3] = 0.f; }
#pragma unroll
        for (int s = 0; s < 4; s++) {
            uint4 A0 = *(const uint4*)&Qt[(R + g) * QSTR + s * 16 + tx4];
            uint4 A1 = *(const uint4*)&Qt[(R + g + 8) * QSTR + s * 16 + tx4];
            u32 ah[4] = { A0.x, A1.x, A0.z, A1.z };
            u32 al[4] = { A0.y, A1.y, A0.w, A1.w };
#pragma unroll
            for (int nt = 0; nt < 8; nt++) {
                uint4 Bq = *(const uint4*)&Kq[(nt * 8 + g) * QSTR + s * 16 + tx4];
                u32 bhv[2] = { Bq.x, Bq.z }, blv[2] = { Bq.y, Bq.w };
                mma16816(S[nt], ah, bhv);
                mma16816(S[nt], ah, blv);
                mma16816(S[nt], al, bhv);
            }
        }
        // ---- exp + pack P ----
        u32 ph01[8], ph23[8], pl01[8], pl23[8];
#pragma unroll
        for (int nt = 0; nt < 8; nt++) {
            float p0 = __expf(S[nt][0] * ATT_SCALE);
            float p1 = __expf(S[nt][1] * ATT_SCALE);
            float p2 = __expf(S[nt][2] * ATT_SCALE);
            float p3 = __expf(S[nt][3] * ATT_SCALE);
            rs0 += p0 + p1; rs1 += p2 + p3;
            split2(p0, p1, ph01[nt], pl01[nt]);
            split2(p2, p3, ph23[nt], pl23[nt]);
        }
        // ---- O += P V ----
#pragma unroll
        for (int s = 0; s < 4; s++) {
            u32 ah[4] = { ph01[2 * s], ph23[2 * s], ph01[2 * s + 1], ph23[2 * s + 1] };
            u32 al[4] = { pl01[2 * s], pl23[2 * s], pl01[2 * s + 1], pl23[2 * s + 1] };
#pragma unroll
            for (int et = 0; et < 8; et++) {
                uint4 Bq = *(const uint4*)&Vq[(et * 8 + g) * QSTR + s * 16 + tx4];
                u32 bhv[2] = { Bq.x, Bq.z }, blv[2] = { Bq.y, Bq.w };
                mma16816(O[et], ah, bhv);
                mma16816(O[et], ah, blv);
                mma16816(O[et], al, bhv);
            }
        }
    }
    __syncthreads();

    rs0 += __shfl_xor_sync(0xffffffffu, rs0, 1); rs0 += __shfl_xor_sync(0xffffffffu, rs0, 2);
    rs1 += __shfl_xor_sync(0xffffffffu, rs1, 1); rs1 += __shfl_xor_sync(0xffffffffu, rs1, 2);
    const float inv0 = 1.f / rs0, inv1 = 1.f / rs1;
#pragma unroll
    for (int et = 0; et < 8; et++) {
        int c = et * 8 + 2 * t;
        OS[(R + g) * STR + c]         = O[et][0] * inv0;
        OS[(R + g) * STR + c + 1]     = O[et][1] * inv0;
        OS[(R + g + 8) * STR + c]     = O[et][2] * inv1;
        OS[(R + g + 8) * STR + c + 1] = O[et][3] * inv1;
    }

    // ---------- epilogue ----------
    for (int i = tid; i < 4096; i += 128) {
        int a = i >> 6, b = i & 63;
        Wlt[b * STR + a] = Wl[i];
    }
    {
        const float* kvt = &g_kvtot[bh * 4096];
        const float* kvb = &g_kv[(size_t)bh * NBLK * 4096];
        const int o0 = tid * 32;
#pragma unroll
        for (int u = 0; u < 8; u++) {
            int o = o0 + 4 * u;
            float4 a = *(const float4*)&kvt[o];
#pragma unroll
            for (int j = 0; j < TK; j++) {
                float4 b4 = *(const float4*)&kvb[(size_t)lut[j] * 4096 + o];
                a.x -= b4.x; a.y -= b4.y; a.z -= b4.z; a.w -= b4.w;
            }
            *(float4*)&KVns[(o >> 6) * STR + (o & 63)] = a;
        }
    }
    if (tid >= 64) {
        const int r = tid - 64;
        float zz = g_ztot[bh * 64 + r];
#pragma unroll
        for (int j = 0; j < TK; j++) zz -= g_z[((size_t)bh * NBLK + lut[j]) * 64 + r];
        zns[r] = zz;
    } else {
        const int r = tid;
        const int sig = (r >> 1) & 3;
        float mx = -1e30f;
#pragma unroll
        for (int p = 0; p < 32; p++) {
            int off = r * QSTR + (p >> 3) * 16 + (((p & 3) ^ sig) << 2) + (((p >> 2) & 1) << 1);
            u32 h = Qt[off], l = Qt[off + 1];
            float e0 = lo_f(h) + lo_f(l), e1 = hi_f(h) + hi_f(l);
            mx = fmaxf(mx, fmaxf(e0, e1));
        }
        float s = 0.f;
#pragma unroll
        for (int p = 0; p < 32; p++) {
            int off = r * QSTR + (p >> 3) * 16 + (((p & 3) ^ sig) << 2) + (((p >> 2) & 1) << 1);
            u32 h = Qt[off], l = Qt[off + 1];
            float e0 = __expf(lo_f(h) + lo_f(l) - mx);
            float e1 = __expf(hi_f(h) + hi_f(l) - mx);
            PhiT[(2 * p) * STR + r] = e0; PhiT[(2 * p + 1) * STR + r] = e1;
            s += e0 + e1;
        }
        float inv = 1.f / s;
#pragma unroll
        for (int d = 0; d < 64; d++) PhiT[d * STR + r] *= inv;
    }
    __syncthreads();

    const int tr = tid >> 4, tc = tid & 15;
    const int r0 = tr * 8, c0 = tc * 4;

    // Ol = (phi(q) @ KVns) / (phi(q).zns + 1e-6)
    {
        ull n01[8], n23[8]; float den[8];
#pragma unroll
        for (int i = 0; i < 8; i++) { n01[i] = 0ull; n23[i] = 0ull; den[i] = 0.f; }
#pragma unroll 8
        for (int d = 0; d < 64; d++) {
            float4 qa = *(const float4*)&PhiT[d * STR + r0];
            float4 qb = *(const float4*)&PhiT[d * STR + r0 + 4];
            ulonglong2 kk = *(const ulonglong2*)&KVns[d * STR + c0];
            float zd = zns[d];
            ull w;
            w = splat2(qa.x); n01[0] = fma2(w, kk.x, n01[0]); n23[0] = fma2(w, kk.y, n23[0]); den[0] = fmaf(qa.x, zd, den[0]);
            w = splat2(qa.y); n01[1] = fma2(w, kk.x, n01[1]); n23[1] = fma2(w, kk.y, n23[1]); den[1] = fmaf(qa.y, zd, den[1]);
            w = splat2(qa.z); n01[2] = fma2(w, kk.x, n01[2]); n23[2] = fma2(w, kk.y, n23[2]); den[2] = fmaf(qa.z, zd, den[2]);
            w = splat2(qa.w); n01[3] = fma2(w, kk.x, n01[3]); n23[3] = fma2(w, kk.y, n23[3]); den[3] = fmaf(qa.w, zd, den[3]);
            w = splat2(qb.x); n01[4] = fma2(w, kk.x, n01[4]); n23[4] = fma2(w, kk.y, n23[4]); den[4] = fmaf(qb.x, zd, den[4]);
            w = splat2(qb.y); n01[5] = fma2(w, kk.x, n01[5]); n23[5] = fma2(w, kk.y, n23[5]); den[5] = fmaf(qb.y, zd, den[5]);
            w = splat2(qb.z); n01[6] = fma2(w, kk.x, n01[6]); n23[6] = fma2(w, kk.y, n23[6]); den[6] = fmaf(qb.z, zd, den[6]);
            w = splat2(qb.w); n01[7] = fma2(w, kk.x, n01[7]); n23[7] = fma2(w, kk.y, n23[7]); den[7] = fmaf(qb.w, zd, den[7]);
        }
#pragma unroll
        for (int ri = 0; ri < 8; ri++) {
            float inv = 1.f / (den[ri] + 1e-6f);
            float a, b, c2, d2; upk2(n01[ri], a, b); upk2(n23[ri], c2, d2);
            *(float4*)&OlS[(r0 + ri) * STR + c0] = make_float4(a * inv, b * inv, c2 * inv, d2 * inv);
        }
    }
    __syncthreads();

    // out = OS + Ol @ Wl^T + bl
    {
        ull a01[8], a23[8];
#pragma unroll
        for (int i = 0; i < 8; i++) { a01[i] = 0ull; a23[i] = 0ull; }
#pragma unroll 4
        for (int d = 0; d < 64; d++) {
            ulonglong2 ww = *(const ulonglong2*)&Wlt[d * STR + c0];
            const float* orow = &OlS[d];
            ull w;
            w = splat2(orow[(r0 + 0) * STR]); a01[0] = fma2(w, ww.x, a01[0]); a23[0] = fma2(w, ww.y, a23[0]);
            w = splat2(orow[(r0 + 1) * STR]); a01[1] = fma2(w, ww.x, a01[1]); a23[1] = fma2(w, ww.y, a23[1]);
            w = splat2(orow[(r0 + 2) * STR]); a01[2] = fma2(w, ww.x, a01[2]); a23[2] = fma2(w, ww.y, a23[2]);
            w = splat2(orow[(r0 + 3) * STR]); a01[3] = fma2(w, ww.x, a01[3]); a23[3] = fma2(w, ww.y, a23[3]);
            w = splat2(orow[(r0 + 4) * STR]); a01[4] = fma2(w, ww.x, a01[4]); a23[4] = fma2(w, ww.y, a23[4]);
            w = splat2(orow[(r0 + 5) * STR]); a01[5] = fma2(w, ww.x, a01[5]); a23[5] = fma2(w, ww.y, a23[5]);
            w = splat2(orow[(r0 + 6) * STR]); a01[6] = fma2(w, ww.x, a01[6]); a23[6] = fma2(w, ww.y, a23[6]);
            w = splat2(orow[(r0 + 7) * STR]); a01[7] = fma2(w, ww.x, a01[7]); a23[7] = fma2(w, ww.y, a23[7]);
        }
        float4 bv = *(const float4*)&bl[c0];
#pragma unroll
        for (int ri = 0; ri < 8; ri++) {
            float a, b, c2, d2; upk2(a01[ri], a, b); upk2(a23[ri], c2, d2);
            float4 osv = *(const float4*)&OS[(r0 + ri) * STR + c0];
            *(float4*)&out[qbase + (size_t)(r0 + ri) * 64 + c0] =
                make_float4(a + bv.x + osv.x, b + bv.y + osv.y,
                            c2 + bv.z + osv.z, d2 + bv.w + osv.w);
        }
    }
}

// ================= launcher =================
extern "C" void kernel_launch(void* const* d_in, const int* in_sizes, int n_in,
                              void* d_out, int out_size) {
    const float* q  = (const float*)d_in[0];
    const float* k  = (const float*)d_in[1];
    const float* v  = (const float*)d_in[2];
    const float* Wl = (const float*)d_in[3];
    const float* bl = (const float*)d_in[4];
    float* out = (float*)d_out;

    // Qt 20,480 + union( K+V quad 40,960 ; epilogue 87,296 ) = 107,776
    const int union_bytes = 5 * 64 * STR * 4 + 256;
    const int smem_bytes  = 64 * QSTR * 4 + union_bytes;
    cudaFuncSetAttribute(attn_kernel, cudaFuncAttributeMaxDynamicSharedMemorySize, smem_bytes);

    kvpool_kernel<<<BH * NBLK, 256>>>(q, k, v);
    topk_kernel<<<BH * NBLK, 64>>>();
    total_kernel<<<dim3(BH, 16), 256>>>();
    attn_kernel<<<BH * NBLK, 128, smem_bytes>>>(q, k, v, Wl, bl, out);
}

// round 11
// speedup vs baseline: 1.1978x; 1.1978x over previous
#include <cuda_runtime.h>
#include <cuda_bf16.h>
#include <cstdint>

#define BH    32
#define LSEQ  4096
#define DDIM  64
#define NBLK  64
#define TK    6
#define STR   68          // fp32 epilogue stride
#define PSTR  36          // bf16x2 pair-row stride in u32 (conflict-free frags)
#define ATT_SCALE 0.125f

typedef unsigned long long ull;
typedef unsigned int u32;

// ---------------- f32x2 packed helpers ----------------
__device__ __forceinline__ ull fma2(ull a, ull b, ull c) {
    ull d; asm("fma.rn.f32x2 %0,%1,%2,%3;" : "=l"(d) : "l"(a), "l"(b), "l"(c)); return d;
}
__device__ __forceinline__ ull splat2(float a) {
    ull r; asm("mov.b64 %0,{%1,%1};" : "=l"(r) : "f"(a)); return r;
}
__device__ __forceinline__ void upk2(ull x, float& a, float& b) {
    asm("mov.b64 {%0,%1},%2;" : "=f"(a), "=f"(b) : "l"(x));
}

// ---------------- bf16 split helpers ----------------
__device__ __forceinline__ u32 packbf(float e, float o) {
    u32 r; asm("cvt.rn.bf16x2.f32 %0,%1,%2;" : "=r"(r) : "f"(o), "f"(e)); return r;
}
__device__ __forceinline__ float lo_f(u32 u) { return __uint_as_float(u << 16); }
__device__ __forceinline__ float hi_f(u32 u) { return __uint_as_float(u & 0xffff0000u); }
__device__ __forceinline__ void split2(float f0, float f1, u32& h, u32& l) {
    h = packbf(f0, f1);
    l = packbf(f0 - lo_f(h), f1 - hi_f(h));
}

// ---------------- mma.sync m16n8k16 bf16 ----------------
__device__ __forceinline__ void mma16816(float* c, const u32* a, const u32* b) {
    asm("mma.sync.aligned.m16n8k16.row.col.f32.bf16.bf16.f32 "
        "{%0,%1,%2,%3},{%4,%5,%6,%7},{%8,%9},{%0,%1,%2,%3};"
        : "+f"(c[0]), "+f"(c[1]), "+f"(c[2]), "+f"(c[3])
        : "r"(a[0]), "r"(a[1]), "r"(a[2]), "r"(a[3]), "r"(b[0]), "r"(b[1]));
}

// ---------------- device scratch ----------------
__device__ float g_qmean[BH * NBLK * DDIM];
__device__ float g_kmean[BH * NBLK * DDIM];
__device__ int   g_lut[BH * NBLK * TK];
__device__ float g_kv[(size_t)BH * NBLK * DDIM * DDIM];
__device__ float g_z[BH * NBLK * DDIM];
__device__ float g_kvtot[BH * DDIM * DDIM];
__device__ float g_ztot[BH * DDIM];

// ================= K1: fused mean-pool + per-block kv/z =================
__global__ void __launch_bounds__(256) kvpool_kernel(
    const float* __restrict__ q, const float* __restrict__ k, const float* __restrict__ v)
{
    __shared__ __align__(16) float Ks[64 * 65];
    __shared__ __align__(16) float Vs[64 * STR];
    const int tid = threadIdx.x;
    const size_t base = (size_t)blockIdx.x * 4096;
    for (int i = tid; i < 4096; i += 256)
        Ks[(i >> 6) * 65 + (i & 63)] = k[base + i];
    for (int i4 = tid; i4 < 1024; i4 += 256) {
        int c = i4 >> 4, e = (i4 & 15) * 4;
        *(float4*)&Vs[c * STR + e] = *(const float4*)&v[base + c * 64 + e];
    }
    __syncthreads();
    if (tid < 64) {
        float s = 0.f;
#pragma unroll
        for (int m = 0; m < 64; m++) s += Ks[m * 65 + tid];
        g_kmean[blockIdx.x * 64 + tid] = s * (1.f / 64.f);
    } else if (tid < 128) {
        const int d = tid - 64;
        const float* p = q + base + d;
        float s = 0.f;
#pragma unroll
        for (int m = 0; m < 64; m++) s += p[m * 64];
        g_qmean[blockIdx.x * 64 + d] = s * (1.f / 64.f);
    }
    __syncthreads();
    if (tid < 64) {                       // phi(k): row softmax
        float* row = &Ks[tid * 65];
        float mx = -1e30f;
#pragma unroll
        for (int i = 0; i < 64; i++) mx = fmaxf(mx, row[i]);
        float s = 0.f;
#pragma unroll
        for (int i = 0; i < 64; i++) { float e = __expf(row[i] - mx); row[i] = e; s += e; }
        float inv = 1.f / s;
#pragma unroll
        for (int i = 0; i < 64; i++) row[i] *= inv;
    }
    __syncthreads();
    if (tid < 64) {
        float s = 0.f;
#pragma unroll
        for (int m = 0; m < 64; m++) s += Ks[m * 65 + tid];
        g_z[(size_t)blockIdx.x * 64 + tid] = s;
    }
    const int d = tid & 63;               // per-lane distinct within warp
    const int e0 = (tid >> 6) * 16;       // warp-uniform -> broadcast Vs reads
    ull acc[8];
#pragma unroll
    for (int i = 0; i < 8; i++) acc[i] = 0ull;
#pragma unroll 4
    for (int m = 0; m < 64; m++) {
        ull cc = splat2(Ks[m * 65 + d]);
        const ull* vp = (const ull*)&Vs[m * STR + e0];
#pragma unroll
        for (int t = 0; t < 8; t++) acc[t] = fma2(cc, vp[t], acc[t]);
    }
    float* op = &g_kv[(size_t)blockIdx.x * 4096 + d * 64 + e0];
#pragma unroll
    for (int u = 0; u < 4; u++) {
        float4 f;
        upk2(acc[2 * u], f.x, f.y);
        upk2(acc[2 * u + 1], f.z, f.w);
        *(float4*)&op[4 * u] = f;
    }
}

// ================= K2: block scores + top-6 (warp argmax) =================
__global__ void topk_kernel() {
    __shared__ float km[64 * 65];
    __shared__ float qv[64];
    __shared__ float sc[64];
    const int bh = blockIdx.x >> 6, qi = blockIdx.x & 63;
    const int tid = threadIdx.x;
    for (int i = tid; i < 4096; i += 64) km[(i >> 6) * 65 + (i & 63)] = g_kmean[bh * 4096 + i];
    qv[tid] = g_qmean[bh * 4096 + qi * 64 + tid];
    __syncthreads();
    float s = 0.f;
#pragma unroll
    for (int d = 0; d < 64; d++) s += qv[d] * km[tid * 65 + d];
    sc[tid] = s;
    __syncthreads();
    if (tid < 32) {
        float s0 = sc[tid], s1 = sc[tid + 32];
        int* lp = &g_lut[(bh * 64 + qi) * TK];
#pragma unroll
        for (int t = 0; t < TK; t++) {
            float m = (s1 > s0) ? s1 : s0;
            int idx = (s1 > s0) ? (tid + 32) : tid;
#pragma unroll
            for (int off = 16; off; off >>= 1) {
                float om = __shfl_xor_sync(0xffffffffu, m, off);
                int oi = __shfl_xor_sync(0xffffffffu, idx, off);
                if (om > m || (om == m && oi < idx)) { m = om; idx = oi; }
            }
            if (tid == 0) lp[t] = idx;
            if (idx == tid) s0 = -1e38f;
            if (idx == tid + 32) s1 = -1e38f;
        }
    }
}

// ================= K3: totals over key blocks =================
__global__ void total_kernel() {
    const int bh = blockIdx.x;
    const int o = blockIdx.y * 256 + threadIdx.x;
    const float* p = &g_kv[(size_t)bh * NBLK * 4096 + o];
    float s = 0.f;
#pragma unroll 8
    for (int b = 0; b < NBLK; b++) s += p[(size_t)b * 4096];
    g_kvtot[bh * 4096 + o] = s;
    if (blockIdx.y == 0 && threadIdx.x < 64) {
        float z = 0.f;
#pragma unroll
        for (int b = 0; b < NBLK; b++) z += g_z[((size_t)bh * NBLK + b) * 64 + threadIdx.x];
        g_ztot[bh * 64 + threadIdx.x] = z;
    }
}

// ================= K4: fused sparse attention + linear + proj =================
// 256 threads / 8 warps: warps (w, w+4) share 16 Q-rows, each owns 32 keys (N-split).
// Smem layout/converts identical to the proven PSTR=36 version. Cross-warp O / rowsum
// reduction via two-phase smem add; normalization folded into the final store.
__global__ void __launch_bounds__(256, 2) attn_kernel(
    const float* __restrict__ q, const float* __restrict__ k, const float* __restrict__ v,
    const float* __restrict__ Wl, const float* __restrict__ bl, float* __restrict__ out)
{
    extern __shared__ __align__(16) unsigned char smraw[];
    u32* Qh = (u32*)smraw;                     // [row][pair] 64*36 u32
    u32* Ql = Qh + 64 * PSTR;
    unsigned char* U = (unsigned char*)(Ql + 64 * PSTR);  // union region
    u32* Kh = (u32*)U;                         // [key][pair d]
    u32* Kl = Kh + 64 * PSTR;
    u32* Vh = Kl + 64 * PSTR;                  // [e][pair key ^ swz]
    u32* Vl = Vh + 64 * PSTR;
    float* OS   = (float*)U;                   // epilogue overlay (unnormalized O_sparse)
    float* PhiT = OS   + 64 * STR;
    float* KVns = PhiT + 64 * STR;
    float* OlS  = KVns + 64 * STR;
    float* Wlt  = OlS  + 64 * STR;
    float* zns  = Wlt  + 64 * STR;
    __shared__ int lut[8];
    __shared__ float rsum[64];

    const int tid  = threadIdx.x;
    const int lane = tid & 31;
    const int wid  = tid >> 5;
    const int R    = (wid & 3) * 16;           // warp row base (warps w and w+4 share)
    const int wcol = wid >> 2;                 // 0: keys 0-31, 1: keys 32-63
    const int g    = lane >> 2, t = lane & 3;
    const int bh = blockIdx.x >> 6, qi = blockIdx.x & 63;
    const size_t qbase = ((size_t)bh * LSEQ + qi * 64) * DDIM;

    if (tid < TK) lut[tid] = g_lut[(bh * 64 + qi) * TK + tid];
#pragma unroll
    for (int i = 0; i < 8; i++) {
        int id = tid + 256 * i;
        int c = id >> 5, p = id & 31;
        float2 f = *(const float2*)&q[qbase + c * 64 + 2 * p];
        u32 h, l; split2(f.x, f.y, h, l);
        Qh[c * PSTR + p] = h; Ql[c * PSTR + p] = l;
    }

    float O[8][4];
#pragma unroll
    for (int i = 0; i < 8; i++) { O[i][0] = O[i][1] = O[i][2] = O[i][3] = 0.f; }
    float rs0 = 0.f, rs1 = 0.f;

    for (int j = 0; j < TK; j++) {
        __syncthreads();
        const size_t kbase = ((size_t)bh * LSEQ + lut[j] * 64) * DDIM;
#pragma unroll
        for (int i = 0; i < 8; i++) {
            int id = tid + 256 * i;
            int c = id >> 5, p = id & 31;
            float2 f = *(const float2*)&k[kbase + c * 64 + 2 * p];
            u32 h, l; split2(f.x, f.y, h, l);
            Kh[c * PSTR + p] = h; Kl[c * PSTR + p] = l;
        }
#pragma unroll
        for (int i = 0; i < 8; i++) {
            int id = tid + 256 * i;
            int e = id & 63, pp = id >> 6;
            float a = v[kbase + (2 * pp) * 64 + e];
            float b = v[kbase + (2 * pp + 1) * 64 + e];
            u32 h, l; split2(a, b, h, l);
            int psw = pp ^ ((e >> 3) & 3);
            Vh[e * PSTR + psw] = h; Vl[e * PSTR + psw] = l;
        }
        __syncthreads();

        // ---- S = Q K^T over this warp's 32 keys (4 local n-tiles) ----
        float S[4][4];
#pragma unroll
        for (int i = 0; i < 4; i++) { S[i][0] = S[i][1] = S[i][2] = S[i][3] = 0.f; }
        const int ao0 = (R + g) * PSTR + t, ao1 = (R + g + 8) * PSTR + t;
#pragma unroll
        for (int s = 0; s < 4; s++) {
            u32 ah[4], al[4];
            ah[0] = Qh[ao0 + s * 8];     ah[1] = Qh[ao1 + s * 8];
            ah[2] = Qh[ao0 + s * 8 + 4]; ah[3] = Qh[ao1 + s * 8 + 4];
            al[0] = Ql[ao0 + s * 8];     al[1] = Ql[ao1 + s * 8];
            al[2] = Ql[ao0 + s * 8 + 4]; al[3] = Ql[ao1 + s * 8 + 4];
#pragma unroll
            for (int nt = 0; nt < 4; nt++) {
                int bo = ((wcol * 4 + nt) * 8 + g) * PSTR + s * 8 + t;
                u32 bhv[2] = { Kh[bo], Kh[bo + 4] };
                u32 blv[2] = { Kl[bo], Kl[bo + 4] };
                mma16816(S[nt], ah, bhv);
                mma16816(S[nt], ah, blv);
                mma16816(S[nt], al, bhv);
            }
        }
        // ---- exp + pack P (this warp's keys only) ----
        u32 ph01[4], ph23[4], pl01[4], pl23[4];
#pragma unroll
        for (int nt = 0; nt < 4; nt++) {
            float p0 = __expf(S[nt][0] * ATT_SCALE);
            float p1 = __expf(S[nt][1] * ATT_SCALE);
            float p2 = __expf(S[nt][2] * ATT_SCALE);
            float p3 = __expf(S[nt][3] * ATT_SCALE);
            rs0 += p0 + p1; rs1 += p2 + p3;
            split2(p0, p1, ph01[nt], pl01[nt]);
            split2(p2, p3, ph23[nt], pl23[nt]);
        }
        // ---- O += P V (partial over this warp's 32 keys, full e range) ----
#pragma unroll
        for (int s = 0; s < 2; s++) {
            u32 ah[4] = { ph01[2 * s], ph23[2 * s], ph01[2 * s + 1], ph23[2 * s + 1] };
            u32 al[4] = { pl01[2 * s], pl23[2 * s], pl01[2 * s + 1], pl23[2 * s + 1] };
#pragma unroll
            for (int et = 0; et < 8; et++) {
                int x = et & 3;
                int bo = (et * 8 + g) * PSTR + wcol * 16 + s * 8 + (t ^ x);
                u32 bhv[2] = { Vh[bo], Vh[bo + 4] };
                u32 blv[2] = { Vl[bo], Vl[bo + 4] };
                mma16816(O[et], ah, bhv);
                mma16816(O[et], ah, blv);
                mma16816(O[et], al, bhv);
            }
        }
    }
    __syncthreads();   // all PV reads done before OS overlays K/V region

    // quad-reduce partial row sums (over this warp's 16 lanes' column pairs)
    rs0 += __shfl_xor_sync(0xffffffffu, rs0, 1); rs0 += __shfl_xor_sync(0xffffffffu, rs0, 2);
    rs1 += __shfl_xor_sync(0xffffffffu, rs1, 1); rs1 += __shfl_xor_sync(0xffffffffu, rs1, 2);

    // two-phase cross-warp reduction into OS / rsum
    if (wcol == 0) {
        if (t == 0) { rsum[R + g] = rs0; rsum[R + g + 8] = rs1; }
#pragma unroll
        for (int et = 0; et < 8; et++) {
            int c = et * 8 + 2 * t;
            OS[(R + g) * STR + c]         = O[et][0];
            OS[(R + g) * STR + c + 1]     = O[et][1];
            OS[(R + g + 8) * STR + c]     = O[et][2];
            OS[(R + g + 8) * STR + c + 1] = O[et][3];
        }
    }
    __syncthreads();
    if (wcol == 1) {
        if (t == 0) { rsum[R + g] += rs0; rsum[R + g + 8] += rs1; }
#pragma unroll
        for (int et = 0; et < 8; et++) {
            int c = et * 8 + 2 * t;
            OS[(R + g) * STR + c]         += O[et][0];
            OS[(R + g) * STR + c + 1]     += O[et][1];
            OS[(R + g + 8) * STR + c]     += O[et][2];
            OS[(R + g + 8) * STR + c + 1] += O[et][3];
        }
    }
    __syncthreads();

    // ---------- epilogue ----------
    for (int i = tid; i < 4096; i += 256) {
        int a = i >> 6, b = i & 63;
        Wlt[b * STR + a] = Wl[i];
    }
    {
        const float* kvt = &g_kvtot[bh * 4096];
        const float* kvb = &g_kv[(size_t)bh * NBLK * 4096];
        const int o0 = tid * 16;
#pragma unroll
        for (int u = 0; u < 4; u++) {
            int o = o0 + 4 * u;
            float4 a = *(const float4*)&kvt[o];
#pragma unroll
            for (int j = 0; j < TK; j++) {
                float4 b4 = *(const float4*)&kvb[(size_t)lut[j] * 4096 + o];
                a.x -= b4.x; a.y -= b4.y; a.z -= b4.z; a.w -= b4.w;
            }
            *(float4*)&KVns[(o >> 6) * STR + (o & 63)] = a;
        }
    }
    if (tid < 64) {
        // phi(q): softmax over head dim for row tid
        const int r = tid;
        float mx = -1e30f;
#pragma unroll
        for (int p = 0; p < 32; p++) {
            u32 h = Qh[r * PSTR + p], l = Ql[r * PSTR + p];
            float e0 = lo_f(h) + lo_f(l), e1 = hi_f(h) + hi_f(l);
            mx = fmaxf(mx, fmaxf(e0, e1));
        }
        float s = 0.f;
#pragma unroll
        for (int p = 0; p < 32; p++) {
            u32 h = Qh[r * PSTR + p], l = Ql[r * PSTR + p];
            float e0 = __expf(lo_f(h) + lo_f(l) - mx);
            float e1 = __expf(hi_f(h) + hi_f(l) - mx);
            PhiT[(2 * p) * STR + r] = e0; PhiT[(2 * p + 1) * STR + r] = e1;
            s += e0 + e1;
        }
        float inv = 1.f / s;
#pragma unroll
        for (int d = 0; d < 64; d++) PhiT[d * STR + r] *= inv;
    } else if (tid < 128) {
        const int r = tid - 64;
        float zz = g_ztot[bh * 64 + r];
#pragma unroll
        for (int j = 0; j < TK; j++) zz -= g_z[((size_t)bh * NBLK + lut[j]) * 64 + r];
        zns[r] = zz;
    } else if (tid < 192) {
        const int r = tid - 128;
        rsum[r] = 1.f / rsum[r];     // invert once; final store multiplies
    }
    __syncthreads();

    const int tr = tid >> 4, tc = tid & 15;
    const int r0 = tr * 4, c0 = tc * 4;     // 4x4 tile per thread at 256 threads

    // Ol = (phi(q) @ KVns) / (phi(q).zns + 1e-6)
    {
        ull n01[4], n23[4]; float den[4];
#pragma unroll
        for (int i = 0; i < 4; i++) { n01[i] = 0ull; n23[i] = 0ull; den[i] = 0.f; }
#pragma unroll 8
        for (int d = 0; d < 64; d++) {
            float4 qa = *(const float4*)&PhiT[d * STR + r0];
            ulonglong2 kk = *(const ulonglong2*)&KVns[d * STR + c0];
            float zd = zns[d];
            ull w;
            w = splat2(qa.x); n01[0] = fma2(w, kk.x, n01[0]); n23[0] = fma2(w, kk.y, n23[0]); den[0] = fmaf(qa.x, zd, den[0]);
            w = splat2(qa.y); n01[1] = fma2(w, kk.x, n01[1]); n23[1] = fma2(w, kk.y, n23[1]); den[1] = fmaf(qa.y, zd, den[1]);
            w = splat2(qa.z); n01[2] = fma2(w, kk.x, n01[2]); n23[2] = fma2(w, kk.y, n23[2]); den[2] = fmaf(qa.z, zd, den[2]);
            w = splat2(qa.w); n01[3] = fma2(w, kk.x, n01[3]); n23[3] = fma2(w, kk.y, n23[3]); den[3] = fmaf(qa.w, zd, den[3]);
        }
#pragma unroll
        for (int ri = 0; ri < 4; ri++) {
            float inv = 1.f / (den[ri] + 1e-6f);
            float a, b, c2, d2; upk2(n01[ri], a, b); upk2(n23[ri], c2, d2);
            *(float4*)&OlS[(r0 + ri) * STR + c0] = make_float4(a * inv, b * inv, c2 * inv, d2 * inv);
        }
    }
    __syncthreads();

    // out = OS/rsum + Ol @ Wl^T + bl
    {
        ull a01[4], a23[4];
#pragma unroll
        for (int i = 0; i < 4; i++) { a01[i] = 0ull; a23[i] = 0ull; }
#pragma unroll 4
        for (int d = 0; d < 64; d++) {
            ulonglong2 ww = *(const ulonglong2*)&Wlt[d * STR + c0];
            const float* orow = &OlS[d];
            ull w;
            w = splat2(orow[(r0 + 0) * STR]); a01[0] = fma2(w, ww.x, a01[0]); a23[0] = fma2(w, ww.y, a23[0]);
            w = splat2(orow[(r0 + 1) * STR]); a01[1] = fma2(w, ww.x, a01[1]); a23[1] = fma2(w, ww.y, a23[1]);
            w = splat2(orow[(r0 + 2) * STR]); a01[2] = fma2(w, ww.x, a01[2]); a23[2] = fma2(w, ww.y, a23[2]);
            w = splat2(orow[(r0 + 3) * STR]); a01[3] = fma2(w, ww.x, a01[3]); a23[3] = fma2(w, ww.y, a23[3]);
        }
        float4 bv = *(const float4*)&bl[c0];
#pragma unroll
        for (int ri = 0; ri < 4; ri++) {
            float a, b, c2, d2; upk2(a01[ri], a, b); upk2(a23[ri], c2, d2);
            float invr = rsum[r0 + ri];
            float4 osv = *(const float4*)&OS[(r0 + ri) * STR + c0];
            *(float4*)&out[qbase + (size_t)(r0 + ri) * 64 + c0] =
                make_float4(a + bv.x + osv.x * invr, b + bv.y + osv.y * invr,
                            c2 + bv.z + osv.z * invr, d2 + bv.w + osv.w * invr);
        }
    }
}

// ================= launcher =================
extern "C" void kernel_launch(void* const* d_in, const int* in_sizes, int n_in,
                              void* d_out, int out_size) {
    const float* q  = (const float*)d_in[0];
    const float* k  = (const float*)d_in[1];
    const float* v  = (const float*)d_in[2];
    const float* Wl = (const float*)d_in[3];
    const float* bl = (const float*)d_in[4];
    float* out = (float*)d_out;

    const int union_bytes = 5 * 64 * STR * 4 + 256;           // 87,296
    const int smem_bytes  = 2 * 64 * PSTR * 4 + union_bytes;  // 105,728
    cudaFuncSetAttribute(attn_kernel, cudaFuncAttributeMaxDynamicSharedMemorySize, smem_bytes);

    kvpool_kernel<<<BH * NBLK, 256>>>(q, k, v);
    topk_kernel<<<BH * NBLK, 64>>>();
    total_kernel<<<dim3(BH, 16), 256>>>();
    attn_kernel<<<BH * NBLK, 256, smem_bytes>>>(q, k, v, Wl, bl, out);
}

// round 13
// speedup vs baseline: 1.2424x; 1.0372x over previous
#include <cuda_runtime.h>
#include <cuda_bf16.h>
#include <cstdint>

#define BH    32
#define LSEQ  4096
#define DDIM  64
#define NBLK  64
#define TK    6
#define STR   68          // fp32 epilogue stride
#define PSTR  36          // bf16x2 pair-row stride in u32 (conflict-free frags)
#define ATT_SCALE 0.125f

typedef unsigned long long ull;
typedef unsigned int u32;

// ---------------- f32x2 packed helpers ----------------
__device__ __forceinline__ ull fma2(ull a, ull b, ull c) {
    ull d; asm("fma.rn.f32x2 %0,%1,%2,%3;" : "=l"(d) : "l"(a), "l"(b), "l"(c)); return d;
}
__device__ __forceinline__ ull splat2(float a) {
    ull r; asm("mov.b64 %0,{%1,%1};" : "=l"(r) : "f"(a)); return r;
}
__device__ __forceinline__ void upk2(ull x, float& a, float& b) {
    asm("mov.b64 {%0,%1},%2;" : "=f"(a), "=f"(b) : "l"(x));
}

// ---------------- bf16 split helpers ----------------
__device__ __forceinline__ u32 packbf(float e, float o) {
    u32 r; asm("cvt.rn.bf16x2.f32 %0,%1,%2;" : "=r"(r) : "f"(o), "f"(e)); return r;
}
__device__ __forceinline__ float lo_f(u32 u) { return __uint_as_float(u << 16); }
__device__ __forceinline__ float hi_f(u32 u) { return __uint_as_float(u & 0xffff0000u); }
__device__ __forceinline__ void split2(float f0, float f1, u32& h, u32& l) {
    h = packbf(f0, f1);
    l = packbf(f0 - lo_f(h), f1 - hi_f(h));
}

// ---------------- mma.sync m16n8k16 bf16 ----------------
__device__ __forceinline__ void mma16816(float* c, const u32* a, const u32* b) {
    asm("mma.sync.aligned.m16n8k16.row.col.f32.bf16.bf16.f32 "
        "{%0,%1,%2,%3},{%4,%5,%6,%7},{%8,%9},{%0,%1,%2,%3};"
        : "+f"(c[0]), "+f"(c[1]), "+f"(c[2]), "+f"(c[3])
        : "r"(a[0]), "r"(a[1]), "r"(a[2]), "r"(a[3]), "r"(b[0]), "r"(b[1]));
}

// ---------------- device scratch ----------------
__device__ float g_qmean[BH * NBLK * DDIM];
__device__ float g_kmean[BH * NBLK * DDIM];
__device__ int   g_lut[BH * NBLK * TK];
__device__ float g_kv[(size_t)BH * NBLK * DDIM * DDIM];
__device__ float g_z[BH * NBLK * DDIM];
__device__ float g_kvtot[BH * DDIM * DDIM];
__device__ float g_ztot[BH * DDIM];

// ================= K1: fused mean-pool + per-block kv/z =================
// All reduction sections use 256 threads (4/row or 4/col + quad shfl).
// NOTE: __syncthreads() between the mean reads (all rows of Ks) and the in-place
// softmax writes is load-bearing — removing it was R12's correctness bug.
__global__ void __launch_bounds__(256) kvpool_kernel(
    const float* __restrict__ q, const float* __restrict__ k, const float* __restrict__ v)
{
    __shared__ __align__(16) float Ks[64 * 65];
    __shared__ __align__(16) float Vs[64 * STR];
    const int tid = threadIdx.x;
    const size_t base = (size_t)blockIdx.x * 4096;
    for (int i = tid; i < 4096; i += 256)
        Ks[(i >> 6) * 65 + (i & 63)] = k[base + i];
    for (int i4 = tid; i4 < 1024; i4 += 256) {
        int c = i4 >> 4, e = (i4 & 15) * 4;
        *(float4*)&Vs[c * STR + e] = *(const float4*)&v[base + c * 64 + e];
    }
    __syncthreads();

    const int quad = tid >> 2, qd = tid & 3;   // 64 quads of 4 threads
    // ---- k-mean (from smem) + q-mean (from gmem), column 'quad', rows split 4-way ----
    {
        float s = 0.f, sq = 0.f;
        const float* qp = q + base + quad;
#pragma unroll
        for (int i = 0; i < 16; i++) {
            int m = qd * 16 + i;
            s  += Ks[m * 65 + quad];
            sq += qp[m * 64];
        }
        s  += __shfl_xor_sync(0xffffffffu, s, 1);  s  += __shfl_xor_sync(0xffffffffu, s, 2);
        sq += __shfl_xor_sync(0xffffffffu, sq, 1); sq += __shfl_xor_sync(0xffffffffu, sq, 2);
        if (qd == 0) {
            g_kmean[blockIdx.x * 64 + quad] = s * (1.f / 64.f);
            g_qmean[blockIdx.x * 64 + quad] = sq * (1.f / 64.f);
        }
    }
    __syncthreads();   // all mean READS of Ks complete before softmax WRITES Ks in place
    // ---- phi(k): row softmax, row 'quad', cols split 4-way ----
    {
        float* row = &Ks[quad * 65 + qd * 16];
        float mx = -1e30f;
#pragma unroll
        for (int i = 0; i < 16; i++) mx = fmaxf(mx, row[i]);
        mx = fmaxf(mx, __shfl_xor_sync(0xffffffffu, mx, 1));
        mx = fmaxf(mx, __shfl_xor_sync(0xffffffffu, mx, 2));
        float s = 0.f;
#pragma unroll
        for (int i = 0; i < 16; i++) { float e = __expf(row[i] - mx); row[i] = e; s += e; }
        s += __shfl_xor_sync(0xffffffffu, s, 1);
        s += __shfl_xor_sync(0xffffffffu, s, 2);
        float inv = 1.f / s;
#pragma unroll
        for (int i = 0; i < 16; i++) row[i] *= inv;
    }
    __syncthreads();
    // ---- z: column sums of phi(k), column 'quad', rows split 4-way ----
    {
        float s = 0.f;
#pragma unroll
        for (int i = 0; i < 16; i++) s += Ks[(qd * 16 + i) * 65 + quad];
        s += __shfl_xor_sync(0xffffffffu, s, 1);
        s += __shfl_xor_sync(0xffffffffu, s, 2);
        if (qd == 0) g_z[(size_t)blockIdx.x * 64 + quad] = s;
    }
    // ---- kv = phi(k)^T V : thread (d, 16-wide e-range), LDS.128 broadcasts ----
    const int d = tid & 63;
    const int e0 = (tid >> 6) * 16;       // warp-uniform
    ull acc[8];
#pragma unroll
    for (int i = 0; i < 8; i++) acc[i] = 0ull;
#pragma unroll 4
    for (int m = 0; m < 64; m++) {
        ull cc = splat2(Ks[m * 65 + d]);
        const ulonglong2* vp = (const ulonglong2*)&Vs[m * STR + e0];
#pragma unroll
        for (int t = 0; t < 4; t++) {
            ulonglong2 vv = vp[t];
            acc[2 * t]     = fma2(cc, vv.x, acc[2 * t]);
            acc[2 * t + 1] = fma2(cc, vv.y, acc[2 * t + 1]);
        }
    }
    float* op = &g_kv[(size_t)blockIdx.x * 4096 + d * 64 + e0];
#pragma unroll
    for (int u = 0; u < 4; u++) {
        float4 f;
        upk2(acc[2 * u], f.x, f.y);
        upk2(acc[2 * u + 1], f.z, f.w);
        *(float4*)&op[4 * u] = f;
    }
}

// ================= K2: block scores + top-6 (warp argmax) =================
__global__ void topk_kernel() {
    __shared__ float km[64 * 65];
    __shared__ float qv[64];
    __shared__ float sc[64];
    const int bh = blockIdx.x >> 6, qi = blockIdx.x & 63;
    const int tid = threadIdx.x;
    for (int i = tid; i < 4096; i += 64) km[(i >> 6) * 65 + (i & 63)] = g_kmean[bh * 4096 + i];
    qv[tid] = g_qmean[bh * 4096 + qi * 64 + tid];
    __syncthreads();
    float s = 0.f;
#pragma unroll
    for (int d = 0; d < 64; d++) s += qv[d] * km[tid * 65 + d];
    sc[tid] = s;
    __syncthreads();
    if (tid < 32) {
        float s0 = sc[tid], s1 = sc[tid + 32];
        int* lp = &g_lut[(bh * 64 + qi) * TK];
#pragma unroll
        for (int t = 0; t < TK; t++) {
            float m = (s1 > s0) ? s1 : s0;
            int idx = (s1 > s0) ? (tid + 32) : tid;
#pragma unroll
            for (int off = 16; off; off >>= 1) {
                float om = __shfl_xor_sync(0xffffffffu, m, off);
                int oi = __shfl_xor_sync(0xffffffffu, idx, off);
                if (om > m || (om == m && oi < idx)) { m = om; idx = oi; }
            }
            if (tid == 0) lp[t] = idx;
            if (idx == tid) s0 = -1e38f;
            if (idx == tid + 32) s1 = -1e38f;
        }
    }
}

// ================= K3: totals over key blocks =================
__global__ void total_kernel() {
    const int bh = blockIdx.x;
    const int o = blockIdx.y * 256 + threadIdx.x;
    const float* p = &g_kv[(size_t)bh * NBLK * 4096 + o];
    float s = 0.f;
#pragma unroll 8
    for (int b = 0; b < NBLK; b++) s += p[(size_t)b * 4096];
    g_kvtot[bh * 4096 + o] = s;
    if (blockIdx.y == 0 && threadIdx.x < 64) {
        float z = 0.f;
#pragma unroll
        for (int b = 0; b < NBLK; b++) z += g_z[((size_t)bh * NBLK + b) * 64 + threadIdx.x];
        g_ztot[bh * 64 + threadIdx.x] = z;
    }
}

// ================= K4: fused sparse attention + linear + proj (R11, unchanged) =================
__global__ void __launch_bounds__(256, 2) attn_kernel(
    const float* __restrict__ q, const float* __restrict__ k, const float* __restrict__ v,
    const float* __restrict__ Wl, const float* __restrict__ bl, float* __restrict__ out)
{
    extern __shared__ __align__(16) unsigned char smraw[];
    u32* Qh = (u32*)smraw;                     // [row][pair] 64*36 u32
    u32* Ql = Qh + 64 * PSTR;
    unsigned char* U = (unsigned char*)(Ql + 64 * PSTR);  // union region
    u32* Kh = (u32*)U;                         // [key][pair d]
    u32* Kl = Kh + 64 * PSTR;
    u32* Vh = Kl + 64 * PSTR;                  // [e][pair key ^ swz]
    u32* Vl = Vh + 64 * PSTR;
    float* OS   = (float*)U;                   // epilogue overlay (unnormalized O_sparse)
    float* PhiT = OS   + 64 * STR;
    float* KVns = PhiT + 64 * STR;
    float* OlS  = KVns + 64 * STR;
    float* Wlt  = OlS  + 64 * STR;
    float* zns  = Wlt  + 64 * STR;
    __shared__ int lut[8];
    __shared__ float rsum[64];

    const int tid  = threadIdx.x;
    const int lane = tid & 31;
    const int wid  = tid >> 5;
    const int R    = (wid & 3) * 16;           // warp row base (warps w and w+4 share)
    const int wcol = wid >> 2;                 // 0: keys 0-31, 1: keys 32-63
    const int g    = lane >> 2, t = lane & 3;
    const int bh = blockIdx.x >> 6, qi = blockIdx.x & 63;
    const size_t qbase = ((size_t)bh * LSEQ + qi * 64) * DDIM;

    if (tid < TK) lut[tid] = g_lut[(bh * 64 + qi) * TK + tid];
#pragma unroll
    for (int i = 0; i < 8; i++) {
        int id = tid + 256 * i;
        int c = id >> 5, p = id & 31;
        float2 f = *(const float2*)&q[qbase + c * 64 + 2 * p];
        u32 h, l; split2(f.x, f.y, h, l);
        Qh[c * PSTR + p] = h; Ql[c * PSTR + p] = l;
    }

    float O[8][4];
#pragma unroll
    for (int i = 0; i < 8; i++) { O[i][0] = O[i][1] = O[i][2] = O[i][3] = 0.f; }
    float rs0 = 0.f, rs1 = 0.f;

    for (int j = 0; j < TK; j++) {
        __syncthreads();
        const size_t kbase = ((size_t)bh * LSEQ + lut[j] * 64) * DDIM;
#pragma unroll
        for (int i = 0; i < 8; i++) {
            int id = tid + 256 * i;
            int c = id >> 5, p = id & 31;
            float2 f = *(const float2*)&k[kbase + c * 64 + 2 * p];
            u32 h, l; split2(f.x, f.y, h, l);
            Kh[c * PSTR + p] = h; Kl[c * PSTR + p] = l;
        }
#pragma unroll
        for (int i = 0; i < 8; i++) {
            int id = tid + 256 * i;
            int e = id & 63, pp = id >> 6;
            float a = v[kbase + (2 * pp) * 64 + e];
            float b = v[kbase + (2 * pp + 1) * 64 + e];
            u32 h, l; split2(a, b, h, l);
            int psw = pp ^ ((e >> 3) & 3);
            Vh[e * PSTR + psw] = h; Vl[e * PSTR + psw] = l;
        }
        __syncthreads();

        // ---- S = Q K^T over this warp's 32 keys ----
        float S[4][4];
#pragma unroll
        for (int i = 0; i < 4; i++) { S[i][0] = S[i][1] = S[i][2] = S[i][3] = 0.f; }
        const int ao0 = (R + g) * PSTR + t, ao1 = (R + g + 8) * PSTR + t;
#pragma unroll
        for (int s = 0; s < 4; s++) {
            u32 ah[4], al[4];
            ah[0] = Qh[ao0 + s * 8];     ah[1] = Qh[ao1 + s * 8];
            ah[2] = Qh[ao0 + s * 8 + 4]; ah[3] = Qh[ao1 + s * 8 + 4];
            al[0] = Ql[ao0 + s * 8];     al[1] = Ql[ao1 + s * 8];
            al[2] = Ql[ao0 + s * 8 + 4]; al[3] = Ql[ao1 + s * 8 + 4];
#pragma unroll
            for (int nt = 0; nt < 4; nt++) {
                int bo = ((wcol * 4 + nt) * 8 + g) * PSTR + s * 8 + t;
                u32 bhv[2] = { Kh[bo], Kh[bo + 4] };
                u32 blv[2] = { Kl[bo], Kl[bo + 4] };
                mma16816(S[nt], ah, bhv);
                mma16816(S[nt], ah, blv);
                mma16816(S[nt], al, bhv);
            }
        }
        // ---- exp + pack P ----
        u32 ph01[4], ph23[4], pl01[4], pl23[4];
#pragma unroll
        for (int nt = 0; nt < 4; nt++) {
            float p0 = __expf(S[nt][0] * ATT_SCALE);
            float p1 = __expf(S[nt][1] * ATT_SCALE);
            float p2 = __expf(S[nt][2] * ATT_SCALE);
            float p3 = __expf(S[nt][3] * ATT_SCALE);
            rs0 += p0 + p1; rs1 += p2 + p3;
            split2(p0, p1, ph01[nt], pl01[nt]);
            split2(p2, p3, ph23[nt], pl23[nt]);
        }
        // ---- O += P V (partial over this warp's 32 keys) ----
#pragma unroll
        for (int s = 0; s < 2; s++) {
            u32 ah[4] = { ph01[2 * s], ph23[2 * s], ph01[2 * s + 1], ph23[2 * s + 1] };
            u32 al[4] = { pl01[2 * s], pl23[2 * s], pl01[2 * s + 1], pl23[2 * s + 1] };
#pragma unroll
            for (int et = 0; et < 8; et++) {
                int x = et & 3;
                int bo = (et * 8 + g) * PSTR + wcol * 16 + s * 8 + (t ^ x);
                u32 bhv[2] = { Vh[bo], Vh[bo + 4] };
                u32 blv[2] = { Vl[bo], Vl[bo + 4] };
                mma16816(O[et], ah, bhv);
                mma16816(O[et], ah, blv);
                mma16816(O[et], al, bhv);
            }
        }
    }
    __syncthreads();

    rs0 += __shfl_xor_sync(0xffffffffu, rs0, 1); rs0 += __shfl_xor_sync(0xffffffffu, rs0, 2);
    rs1 += __shfl_xor_sync(0xffffffffu, rs1, 1); rs1 += __shfl_xor_sync(0xffffffffu, rs1, 2);

    if (wcol == 0) {
        if (t == 0) { rsum[R + g] = rs0; rsum[R + g + 8] = rs1; }
#pragma unroll
        for (int et = 0; et < 8; et++) {
            int c = et * 8 + 2 * t;
            OS[(R + g) * STR + c]         = O[et][0];
            OS[(R + g) * STR + c + 1]     = O[et][1];
            OS[(R + g + 8) * STR + c]     = O[et][2];
            OS[(R + g + 8) * STR + c + 1] = O[et][3];
        }
    }
    __syncthreads();
    if (wcol == 1) {
        if (t == 0) { rsum[R + g] += rs0; rsum[R + g + 8] += rs1; }
#pragma unroll
        for (int et = 0; et < 8; et++) {
            int c = et * 8 + 2 * t;
            OS[(R + g) * STR + c]         += O[et][0];
            OS[(R + g) * STR + c + 1]     += O[et][1];
            OS[(R + g + 8) * STR + c]     += O[et][2];
            OS[(R + g + 8) * STR + c + 1] += O[et][3];
        }
    }
    __syncthreads();

    // ---------- epilogue ----------
    for (int i = tid; i < 4096; i += 256) {
        int a = i >> 6, b = i & 63;
        Wlt[b * STR + a] = Wl[i];
    }
    {
        const float* kvt = &g_kvtot[bh * 4096];
        const float* kvb = &g_kv[(size_t)bh * NBLK * 4096];
        const int o0 = tid * 16;
#pragma unroll
        for (int u = 0; u < 4; u++) {
            int o = o0 + 4 * u;
            float4 a = *(const float4*)&kvt[o];
#pragma unroll
            for (int j = 0; j < TK; j++) {
                float4 b4 = *(const float4*)&kvb[(size_t)lut[j] * 4096 + o];
                a.x -= b4.x; a.y -= b4.y; a.z -= b4.z; a.w -= b4.w;
            }
            *(float4*)&KVns[(o >> 6) * STR + (o & 63)] = a;
        }
    }
    if (tid < 64) {
        const int r = tid;
        float mx = -1e30f;
#pragma unroll
        for (int p = 0; p < 32; p++) {
            u32 h = Qh[r * PSTR + p], l = Ql[r * PSTR + p];
            float e0 = lo_f(h) + lo_f(l), e1 = hi_f(h) + hi_f(l);
            mx = fmaxf(mx, fmaxf(e0, e1));
        }
        float s = 0.f;
#pragma unroll
        for (int p = 0; p < 32; p++) {
            u32 h = Qh[r * PSTR + p], l = Ql[r * PSTR + p];
            float e0 = __expf(lo_f(h) + lo_f(l) - mx);
            float e1 = __expf(hi_f(h) + hi_f(l) - mx);
            PhiT[(2 * p) * STR + r] = e0; PhiT[(2 * p + 1) * STR + r] = e1;
            s += e0 + e1;
        }
        float inv = 1.f / s;
#pragma unroll
        for (int d = 0; d < 64; d++) PhiT[d * STR + r] *= inv;
    } else if (tid < 128) {
        const int r = tid - 64;
        float zz = g_ztot[bh * 64 + r];
#pragma unroll
        for (int j = 0; j < TK; j++) zz -= g_z[((size_t)bh * NBLK + lut[j]) * 64 + r];
        zns[r] = zz;
    } else if (tid < 192) {
        const int r = tid - 128;
        rsum[r] = 1.f / rsum[r];
    }
    __syncthreads();

    const int tr = tid >> 4, tc = tid & 15;
    const int r0 = tr * 4, c0 = tc * 4;

    // Ol = (phi(q) @ KVns) / (phi(q).zns + 1e-6)
    {
        ull n01[4], n23[4]; float den[4];
#pragma unroll
        for (int i = 0; i < 4; i++) { n01[i] = 0ull; n23[i] = 0ull; den[i] = 0.f; }
#pragma unroll 8
        for (int d = 0; d < 64; d++) {
            float4 qa = *(const float4*)&PhiT[d * STR + r0];
            ulonglong2 kk = *(const ulonglong2*)&KVns[d * STR + c0];
            float zd = zns[d];
            ull w;
            w = splat2(qa.x); n01[0] = fma2(w, kk.x, n01[0]); n23[0] = fma2(w, kk.y, n23[0]); den[0] = fmaf(qa.x, zd, den[0]);
            w = splat2(qa.y); n01[1] = fma2(w, kk.x, n01[1]); n23[1] = fma2(w, kk.y, n23[1]); den[1] = fmaf(qa.y, zd, den[1]);
            w = splat2(qa.z); n01[2] = fma2(w, kk.x, n01[2]); n23[2] = fma2(w, kk.y, n23[2]); den[2] = fmaf(qa.z, zd, den[2]);
            w = splat2(qa.w); n01[3] = fma2(w, kk.x, n01[3]); n23[3] = fma2(w, kk.y, n23[3]); den[3] = fmaf(qa.w, zd, den[3]);
        }
#pragma unroll
        for (int ri = 0; ri < 4; ri++) {
            float inv = 1.f / (den[ri] + 1e-6f);
            float a, b, c2, d2; upk2(n01[ri], a, b); upk2(n23[ri], c2, d2);
            *(float4*)&OlS[(r0 + ri) * STR + c0] = make_float4(a * inv, b * inv, c2 * inv, d2 * inv);
        }
    }
    __syncthreads();

    // out = OS/rsum + Ol @ Wl^T + bl
    {
        ull a01[4], a23[4];
#pragma unroll
        for (int i = 0; i < 4; i++) { a01[i] = 0ull; a23[i] = 0ull; }
#pragma unroll 4
        for (int d = 0; d < 64; d++) {
            ulonglong2 ww = *(const ulonglong2*)&Wlt[d * STR + c0];
            const float* orow = &OlS[d];
            ull w;
            w = splat2(orow[(r0 + 0) * STR]); a01[0] = fma2(w, ww.x, a01[0]); a23[0] = fma2(w, ww.y, a23[0]);
            w = splat2(orow[(r0 + 1) * STR]); a01[1] = fma2(w, ww.x, a01[1]); a23[1] = fma2(w, ww.y, a23[1]);
            w = splat2(orow[(r0 + 2) * STR]); a01[2] = fma2(w, ww.x, a01[2]); a23[2] = fma2(w, ww.y, a23[2]);
            w = splat2(orow[(r0 + 3) * STR]); a01[3] = fma2(w, ww.x, a01[3]); a23[3] = fma2(w, ww.y, a23[3]);
        }
        float4 bv = *(const float4*)&bl[c0];
#pragma unroll
        for (int ri = 0; ri < 4; ri++) {
            float a, b, c2, d2; upk2(a01[ri], a, b); upk2(a23[ri], c2, d2);
            float invr = rsum[r0 + ri];
            float4 osv = *(const float4*)&OS[(r0 + ri) * STR + c0];
            *(float4*)&out[qbase + (size_t)(r0 + ri) * 64 + c0] =
                make_float4(a + bv.x + osv.x * invr, b + bv.y + osv.y * invr,
                            c2 + bv.z + osv.z * invr, d2 + bv.w + osv.w * invr);
        }
    }
}

// ================= launcher =================
extern "C" void kernel_launch(void* const* d_in, const int* in_sizes, int n_in,
                              void* d_out, int out_size) {
    const float* q  = (const float*)d_in[0];
    const float* k  = (const float*)d_in[1];
    const float* v  = (const float*)d_in[2];
    const float* Wl = (const float*)d_in[3];
    const float* bl = (const float*)d_in[4];
    float* out = (float*)d_out;

    const int union_bytes = 5 * 64 * STR * 4 + 256;           // 87,296
    const int smem_bytes  = 2 * 64 * PSTR * 4 + union_bytes;  // 105,728
    cudaFuncSetAttribute(attn_kernel, cudaFuncAttributeMaxDynamicSharedMemorySize, smem_bytes);

    kvpool_kernel<<<BH * NBLK, 256>>>(q, k, v);
    topk_kernel<<<BH * NBLK, 64>>>();
    total_kernel<<<dim3(BH, 16), 256>>>();
    attn_kernel<<<BH * NBLK, 256, smem_bytes>>>(q, k, v, Wl, bl, out);
}

// round 14
// speedup vs baseline: 1.2465x; 1.0033x over previous
#include <cuda_runtime.h>
#include <cuda_bf16.h>
#include <cstdint>

#define BH    32
#define LSEQ  4096
#define DDIM  64
#define NBLK  64
#define TK    6
#define STR   68          // fp32 epilogue stride
#define PSTR  36          // bf16x2 pair-row stride in u32 (conflict-free frags)
#define ATT_SCALE 0.125f

typedef unsigned long long ull;
typedef unsigned int u32;

// ---------------- f32x2 packed helpers ----------------
__device__ __forceinline__ ull fma2(ull a, ull b, ull c) {
    ull d; asm("fma.rn.f32x2 %0,%1,%2,%3;" : "=l"(d) : "l"(a), "l"(b), "l"(c)); return d;
}
__device__ __forceinline__ ull splat2(float a) {
    ull r; asm("mov.b64 %0,{%1,%1};" : "=l"(r) : "f"(a)); return r;
}
__device__ __forceinline__ void upk2(ull x, float& a, float& b) {
    asm("mov.b64 {%0,%1},%2;" : "=f"(a), "=f"(b) : "l"(x));
}

// ---------------- bf16 split helpers ----------------
__device__ __forceinline__ u32 packbf(float e, float o) {
    u32 r; asm("cvt.rn.bf16x2.f32 %0,%1,%2;" : "=r"(r) : "f"(o), "f"(e)); return r;
}
__device__ __forceinline__ float lo_f(u32 u) { return __uint_as_float(u << 16); }
__device__ __forceinline__ float hi_f(u32 u) { return __uint_as_float(u & 0xffff0000u); }
__device__ __forceinline__ void split2(float f0, float f1, u32& h, u32& l) {
    h = packbf(f0, f1);
    l = packbf(f0 - lo_f(h), f1 - hi_f(h));
}

// ---------------- mma.sync m16n8k16 bf16 ----------------
__device__ __forceinline__ void mma16816(float* c, const u32* a, const u32* b) {
    asm("mma.sync.aligned.m16n8k16.row.col.f32.bf16.bf16.f32 "
        "{%0,%1,%2,%3},{%4,%5,%6,%7},{%8,%9},{%0,%1,%2,%3};"
        : "+f"(c[0]), "+f"(c[1]), "+f"(c[2]), "+f"(c[3])
        : "r"(a[0]), "r"(a[1]), "r"(a[2]), "r"(a[3]), "r"(b[0]), "r"(b[1]));
}

// ---------------- cp.async helpers ----------------
__device__ __forceinline__ void cp16(u32 saddr, const void* g) {
    asm volatile("cp.async.cg.shared.global [%0], [%1], 16;" :: "r"(saddr), "l"(g));
}
__device__ __forceinline__ void cp_commit() { asm volatile("cp.async.commit_group;"); }
__device__ __forceinline__ void cp_wait0()  { asm volatile("cp.async.wait_group 0;" ::: "memory"); }

// ---------------- device scratch ----------------
__device__ float g_qmean[BH * NBLK * DDIM];
__device__ float g_kmean[BH * NBLK * DDIM];
__device__ int   g_lut[BH * NBLK * TK];
__device__ float g_kv[(size_t)BH * NBLK * DDIM * DDIM];
__device__ float g_z[BH * NBLK * DDIM];
__device__ float g_kvtot[BH * DDIM * DDIM];
__device__ float g_ztot[BH * DDIM];

// ================= K1: fused mean-pool + per-block kv/z (R13, unchanged) =================
__global__ void __launch_bounds__(256) kvpool_kernel(
    const float* __restrict__ q, const float* __restrict__ k, const float* __restrict__ v)
{
    __shared__ __align__(16) float Ks[64 * 65];
    __shared__ __align__(16) float Vs[64 * STR];
    const int tid = threadIdx.x;
    const size_t base = (size_t)blockIdx.x * 4096;
    for (int i = tid; i < 4096; i += 256)
        Ks[(i >> 6) * 65 + (i & 63)] = k[base + i];
    for (int i4 = tid; i4 < 1024; i4 += 256) {
        int c = i4 >> 4, e = (i4 & 15) * 4;
        *(float4*)&Vs[c * STR + e] = *(const float4*)&v[base + c * 64 + e];
    }
    __syncthreads();

    const int quad = tid >> 2, qd = tid & 3;
    {
        float s = 0.f, sq = 0.f;
        const float* qp = q + base + quad;
#pragma unroll
        for (int i = 0; i < 16; i++) {
            int m = qd * 16 + i;
            s  += Ks[m * 65 + quad];
            sq += qp[m * 64];
        }
        s  += __shfl_xor_sync(0xffffffffu, s, 1);  s  += __shfl_xor_sync(0xffffffffu, s, 2);
        sq += __shfl_xor_sync(0xffffffffu, sq, 1); sq += __shfl_xor_sync(0xffffffffu, sq, 2);
        if (qd == 0) {
            g_kmean[blockIdx.x * 64 + quad] = s * (1.f / 64.f);
            g_qmean[blockIdx.x * 64 + quad] = sq * (1.f / 64.f);
        }
    }
    __syncthreads();   // mean READS of Ks before softmax WRITES (load-bearing)
    {
        float* row = &Ks[quad * 65 + qd * 16];
        float mx = -1e30f;
#pragma unroll
        for (int i = 0; i < 16; i++) mx = fmaxf(mx, row[i]);
        mx = fmaxf(mx, __shfl_xor_sync(0xffffffffu, mx, 1));
        mx = fmaxf(mx, __shfl_xor_sync(0xffffffffu, mx, 2));
        float s = 0.f;
#pragma unroll
        for (int i = 0; i < 16; i++) { float e = __expf(row[i] - mx); row[i] = e; s += e; }
        s += __shfl_xor_sync(0xffffffffu, s, 1);
        s += __shfl_xor_sync(0xffffffffu, s, 2);
        float inv = 1.f / s;
#pragma unroll
        for (int i = 0; i < 16; i++) row[i] *= inv;
    }
    __syncthreads();
    {
        float s = 0.f;
#pragma unroll
        for (int i = 0; i < 16; i++) s += Ks[(qd * 16 + i) * 65 + quad];
        s += __shfl_xor_sync(0xffffffffu, s, 1);
        s += __shfl_xor_sync(0xffffffffu, s, 2);
        if (qd == 0) g_z[(size_t)blockIdx.x * 64 + quad] = s;
    }
    const int d = tid & 63;
    const int e0 = (tid >> 6) * 16;
    ull acc[8];
#pragma unroll
    for (int i = 0; i < 8; i++) acc[i] = 0ull;
#pragma unroll 4
    for (int m = 0; m < 64; m++) {
        ull cc = splat2(Ks[m * 65 + d]);
        const ulonglong2* vp = (const ulonglong2*)&Vs[m * STR + e0];
#pragma unroll
        for (int t = 0; t < 4; t++) {
            ulonglong2 vv = vp[t];
            acc[2 * t]     = fma2(cc, vv.x, acc[2 * t]);
            acc[2 * t + 1] = fma2(cc, vv.y, acc[2 * t + 1]);
        }
    }
    float* op = &g_kv[(size_t)blockIdx.x * 4096 + d * 64 + e0];
#pragma unroll
    for (int u = 0; u < 4; u++) {
        float4 f;
        upk2(acc[2 * u], f.x, f.y);
        upk2(acc[2 * u + 1], f.z, f.w);
        *(float4*)&op[4 * u] = f;
    }
}

// ================= K2: block scores + top-6 (R13, unchanged) =================
__global__ void topk_kernel() {
    __shared__ float km[64 * 65];
    __shared__ float qv[64];
    __shared__ float sc[64];
    const int bh = blockIdx.x >> 6, qi = blockIdx.x & 63;
    const int tid = threadIdx.x;
    for (int i = tid; i < 4096; i += 64) km[(i >> 6) * 65 + (i & 63)] = g_kmean[bh * 4096 + i];
    qv[tid] = g_qmean[bh * 4096 + qi * 64 + tid];
    __syncthreads();
    float s = 0.f;
#pragma unroll
    for (int d = 0; d < 64; d++) s += qv[d] * km[tid * 65 + d];
    sc[tid] = s;
    __syncthreads();
    if (tid < 32) {
        float s0 = sc[tid], s1 = sc[tid + 32];
        int* lp = &g_lut[(bh * 64 + qi) * TK];
#pragma unroll
        for (int t = 0; t < TK; t++) {
            float m = (s1 > s0) ? s1 : s0;
            int idx = (s1 > s0) ? (tid + 32) : tid;
#pragma unroll
            for (int off = 16; off; off >>= 1) {
                float om = __shfl_xor_sync(0xffffffffu, m, off);
                int oi = __shfl_xor_sync(0xffffffffu, idx, off);
                if (om > m || (om == m && oi < idx)) { m = om; idx = oi; }
            }
            if (tid == 0) lp[t] = idx;
            if (idx == tid) s0 = -1e38f;
            if (idx == tid + 32) s1 = -1e38f;
        }
    }
}

// ================= K3: totals over key blocks (R13, unchanged) =================
__global__ void total_kernel() {
    const int bh = blockIdx.x;
    const int o = blockIdx.y * 256 + threadIdx.x;
    const float* p = &g_kv[(size_t)bh * NBLK * 4096 + o];
    float s = 0.f;
#pragma unroll 8
    for (int b = 0; b < NBLK; b++) s += p[(size_t)b * 4096];
    g_kvtot[bh * 4096 + o] = s;
    if (blockIdx.y == 0 && threadIdx.x < 64) {
        float z = 0.f;
#pragma unroll
        for (int b = 0; b < NBLK; b++) z += g_z[((size_t)bh * NBLK + b) * 64 + threadIdx.x];
        g_ztot[bh * 64 + threadIdx.x] = z;
    }
}

// ================= K4: attn with cp.async-pipelined K/V staging =================
// Mainloop: while mma(j) runs, cp.async streams raw fp32 K/V of block j+1 into
// smem; the convert phase then reads smem (29cyc) instead of stalling on gmem.
__global__ void __launch_bounds__(256, 2) attn_kernel(
    const float* __restrict__ q, const float* __restrict__ k, const float* __restrict__ v,
    const float* __restrict__ Wl, const float* __restrict__ bl, float* __restrict__ out)
{
    extern __shared__ __align__(16) unsigned char smraw[];
    u32* Qh = (u32*)smraw;                     // [row][pair] 64*36 u32
    u32* Ql = Qh + 64 * PSTR;
    unsigned char* U = (unsigned char*)(Ql + 64 * PSTR);  // union region
    u32* Kh = (u32*)U;                         // pair tiles
    u32* Kl = Kh + 64 * PSTR;
    u32* Vh = Kl + 64 * PSTR;
    u32* Vl = Vh + 64 * PSTR;
    float* Kraw = (float*)(Vl + 64 * PSTR);    // raw fp32 staging, 16 KB
    float* Vraw = Kraw + 4096;                 // 16 KB   (total mainloop 69,632 <= union)
    float* OS   = (float*)U;                   // epilogue overlay
    float* PhiT = OS   + 64 * STR;
    float* KVns = PhiT + 64 * STR;
    float* OlS  = KVns + 64 * STR;
    float* Wlt  = OlS  + 64 * STR;
    float* zns  = Wlt  + 64 * STR;
    __shared__ float rsum[64];

    const int tid  = threadIdx.x;
    const int lane = tid & 31;
    const int wid  = tid >> 5;
    const int R    = (wid & 3) * 16;
    const int wcol = wid >> 2;
    const int g    = lane >> 2, t = lane & 3;
    const int bh = blockIdx.x >> 6, qi = blockIdx.x & 63;
    const size_t qbase = ((size_t)bh * LSEQ + qi * 64) * DDIM;

    // lut in registers (uniform broadcast loads)
    int lutr[TK];
#pragma unroll
    for (int j = 0; j < TK; j++) lutr[j] = g_lut[(bh * 64 + qi) * TK + j];

    const u32 kraw_s = (u32)__cvta_generic_to_shared(Kraw);
    const u32 vraw_s = (u32)__cvta_generic_to_shared(Vraw);

    // prefetch block 0
    {
        const size_t kb = ((size_t)bh * LSEQ + lutr[0] * 64) * DDIM;
#pragma unroll
        for (int i = 0; i < 4; i++) {
            int o = (tid + 256 * i) * 4;
            cp16(kraw_s + o * 4, k + kb + o);
            cp16(vraw_s + o * 4, v + kb + o);
        }
        cp_commit();
    }

    // Q convert (gmem -> pairs)
#pragma unroll
    for (int i = 0; i < 8; i++) {
        int id = tid + 256 * i;
        int c = id >> 5, p = id & 31;
        float2 f = *(const float2*)&q[qbase + c * 64 + 2 * p];
        u32 h, l; split2(f.x, f.y, h, l);
        Qh[c * PSTR + p] = h; Ql[c * PSTR + p] = l;
    }

    float O[8][4];
#pragma unroll
    for (int i = 0; i < 8; i++) { O[i][0] = O[i][1] = O[i][2] = O[i][3] = 0.f; }
    float rs0 = 0.f, rs1 = 0.f;

    for (int j = 0; j < TK; j++) {
        cp_wait0();
        __syncthreads();   // raw landed AND prior iter's mma reads of pair bufs done
        // K convert (smem raw -> pairs)
#pragma unroll
        for (int i = 0; i < 8; i++) {
            int id = tid + 256 * i;
            int c = id >> 5, p = id & 31;
            float2 f = *(const float2*)&Kraw[c * 64 + 2 * p];
            u32 h, l; split2(f.x, f.y, h, l);
            Kh[c * PSTR + p] = h; Kl[c * PSTR + p] = l;
        }
        // V transpose convert (smem raw -> pairs)
#pragma unroll
        for (int i = 0; i < 8; i++) {
            int id = tid + 256 * i;
            int e = id & 63, pp = id >> 6;
            float a = Vraw[(2 * pp) * 64 + e];
            float b = Vraw[(2 * pp + 1) * 64 + e];
            u32 h, l; split2(a, b, h, l);
            int psw = pp ^ ((e >> 3) & 3);
            Vh[e * PSTR + psw] = h; Vl[e * PSTR + psw] = l;
        }
        __syncthreads();   // converts done: raw bufs free, pair bufs ready
        if (j + 1 < TK) {  // stream next block during the mma phase
            const size_t kb = ((size_t)bh * LSEQ + lutr[j + 1] * 64) * DDIM;
#pragma unroll
            for (int i = 0; i < 4; i++) {
                int o = (tid + 256 * i) * 4;
                cp16(kraw_s + o * 4, k + kb + o);
                cp16(vraw_s + o * 4, v + kb + o);
            }
            cp_commit();
        }

        // ---- S = Q K^T over this warp's 32 keys ----
        float S[4][4];
#pragma unroll
        for (int i = 0; i < 4; i++) { S[i][0] = S[i][1] = S[i][2] = S[i][3] = 0.f; }
        const int ao0 = (R + g) * PSTR + t, ao1 = (R + g + 8) * PSTR + t;
#pragma unroll
        for (int s = 0; s < 4; s++) {
            u32 ah[4], al[4];
            ah[0] = Qh[ao0 + s * 8];     ah[1] = Qh[ao1 + s * 8];
            ah[2] = Qh[ao0 + s * 8 + 4]; ah[3] = Qh[ao1 + s * 8 + 4];
            al[0] = Ql[ao0 + s * 8];     al[1] = Ql[ao1 + s * 8];
            al[2] = Ql[ao0 + s * 8 + 4]; al[3] = Ql[ao1 + s * 8 + 4];
#pragma unroll
            for (int nt = 0; nt < 4; nt++) {
                int bo = ((wcol * 4 + nt) * 8 + g) * PSTR + s * 8 + t;
                u32 bhv[2] = { Kh[bo], Kh[bo + 4] };
                u32 blv[2] = { Kl[bo], Kl[bo + 4] };
                mma16816(S[nt], ah, bhv);
                mma16816(S[nt], ah, blv);
                mma16816(S[nt], al, bhv);
            }
        }
        // ---- exp + pack P ----
        u32 ph01[4], ph23[4], pl01[4], pl23[4];
#pragma unroll
        for (int nt = 0; nt < 4; nt++) {
            float p0 = __expf(S[nt][0] * ATT_SCALE);
            float p1 = __expf(S[nt][1] * ATT_SCALE);
            float p2 = __expf(S[nt][2] * ATT_SCALE);
            float p3 = __expf(S[nt][3] * ATT_SCALE);
            rs0 += p0 + p1; rs1 += p2 + p3;
            split2(p0, p1, ph01[nt], pl01[nt]);
            split2(p2, p3, ph23[nt], pl23[nt]);
        }
        // ---- O += P V (partial over this warp's 32 keys) ----
#pragma unroll
        for (int s = 0; s < 2; s++) {
            u32 ah[4] = { ph01[2 * s], ph23[2 * s], ph01[2 * s + 1], ph23[2 * s + 1] };
            u32 al[4] = { pl01[2 * s], pl23[2 * s], pl01[2 * s + 1], pl23[2 * s + 1] };
#pragma unroll
            for (int et = 0; et < 8; et++) {
                int x = et & 3;
                int bo = (et * 8 + g) * PSTR + wcol * 16 + s * 8 + (t ^ x);
                u32 bhv[2] = { Vh[bo], Vh[bo + 4] };
                u32 blv[2] = { Vl[bo], Vl[bo + 4] };
                mma16816(O[et], ah, bhv);
                mma16816(O[et], ah, blv);
                mma16816(O[et], al, bhv);
            }
        }
    }
    __syncthreads();

    rs0 += __shfl_xor_sync(0xffffffffu, rs0, 1); rs0 += __shfl_xor_sync(0xffffffffu, rs0, 2);
    rs1 += __shfl_xor_sync(0xffffffffu, rs1, 1); rs1 += __shfl_xor_sync(0xffffffffu, rs1, 2);

    if (wcol == 0) {
        if (t == 0) { rsum[R + g] = rs0; rsum[R + g + 8] = rs1; }
#pragma unroll
        for (int et = 0; et < 8; et++) {
            int c = et * 8 + 2 * t;
            OS[(R + g) * STR + c]         = O[et][0];
            OS[(R + g) * STR + c + 1]     = O[et][1];
            OS[(R + g + 8) * STR + c]     = O[et][2];
            OS[(R + g + 8) * STR + c + 1] = O[et][3];
        }
    }
    __syncthreads();
    if (wcol == 1) {
        if (t == 0) { rsum[R + g] += rs0; rsum[R + g + 8] += rs1; }
#pragma unroll
        for (int et = 0; et < 8; et++) {
            int c = et * 8 + 2 * t;
            OS[(R + g) * STR + c]         += O[et][0];
            OS[(R + g) * STR + c + 1]     += O[et][1];
            OS[(R + g + 8) * STR + c]     += O[et][2];
            OS[(R + g + 8) * STR + c + 1] += O[et][3];
        }
    }
    __syncthreads();

    // ---------- epilogue ----------
    for (int i = tid; i < 4096; i += 256) {
        int a = i >> 6, b = i & 63;
        Wlt[b * STR + a] = Wl[i];
    }
    {
        const float* kvt = &g_kvtot[bh * 4096];
        const float* kvb = &g_kv[(size_t)bh * NBLK * 4096];
        const int o0 = tid * 16;
#pragma unroll
        for (int u = 0; u < 4; u++) {
            int o = o0 + 4 * u;
            float4 a = *(const float4*)&kvt[o];
#pragma unroll
            for (int j = 0; j < TK; j++) {
                float4 b4 = *(const float4*)&kvb[(size_t)lutr[j] * 4096 + o];
                a.x -= b4.x; a.y -= b4.y; a.z -= b4.z; a.w -= b4.w;
            }
            *(float4*)&KVns[(o >> 6) * STR + (o & 63)] = a;
        }
    }
    if (tid < 64) {
        const int r = tid;
        float mx = -1e30f;
#pragma unroll
        for (int p = 0; p < 32; p++) {
            u32 h = Qh[r * PSTR + p], l = Ql[r * PSTR + p];
            float e0 = lo_f(h) + lo_f(l), e1 = hi_f(h) + hi_f(l);
            mx = fmaxf(mx, fmaxf(e0, e1));
        }
        float s = 0.f;
#pragma unroll
        for (int p = 0; p < 32; p++) {
            u32 h = Qh[r * PSTR + p], l = Ql[r * PSTR + p];
            float e0 = __expf(lo_f(h) + lo_f(l) - mx);
            float e1 = __expf(hi_f(h) + hi_f(l) - mx);
            PhiT[(2 * p) * STR + r] = e0; PhiT[(2 * p + 1) * STR + r] = e1;
            s += e0 + e1;
        }
        float inv = 1.f / s;
#pragma unroll
        for (int d = 0; d < 64; d++) PhiT[d * STR + r] *= inv;
    } else if (tid < 128) {
        const int r = tid - 64;
        float zz = g_ztot[bh * 64 + r];
#pragma unroll
        for (int j = 0; j < TK; j++) zz -= g_z[((size_t)bh * NBLK + lutr[j]) * 64 + r];
        zns[r] = zz;
    } else if (tid < 192) {
        const int r = tid - 128;
        rsum[r] = 1.f / rsum[r];
    }
    __syncthreads();

    const int tr = tid >> 4, tc = tid & 15;
    const int r0 = tr * 4, c0 = tc * 4;

    // Ol = (phi(q) @ KVns) / (phi(q).zns + 1e-6)
    {
        ull n01[4], n23[4]; float den[4];
#pragma unroll
        for (int i = 0; i < 4; i++) { n01[i] = 0ull; n23[i] = 0ull; den[i] = 0.f; }
#pragma unroll 8
        for (int d = 0; d < 64; d++) {
            float4 qa = *(const float4*)&PhiT[d * STR + r0];
            ulonglong2 kk = *(const ulonglong2*)&KVns[d * STR + c0];
            float zd = zns[d];
            ull w;
            w = splat2(qa.x); n01[0] = fma2(w, kk.x, n01[0]); n23[0] = fma2(w, kk.y, n23[0]); den[0] = fmaf(qa.x, zd, den[0]);
            w = splat2(qa.y); n01[1] = fma2(w, kk.x, n01[1]); n23[1] = fma2(w, kk.y, n23[1]); den[1] = fmaf(qa.y, zd, den[1]);
            w = splat2(qa.z); n01[2] = fma2(w, kk.x, n01[2]); n23[2] = fma2(w, kk.y, n23[2]); den[2] = fmaf(qa.z, zd, den[2]);
            w = splat2(qa.w); n01[3] = fma2(w, kk.x, n01[3]); n23[3] = fma2(w, kk.y, n23[3]); den[3] = fmaf(qa.w, zd, den[3]);
        }
#pragma unroll
        for (int ri = 0; ri < 4; ri++) {
            float inv = 1.f / (den[ri] + 1e-6f);
            float a, b, c2, d2; upk2(n01[ri], a, b); upk2(n23[ri], c2, d2);
            *(float4*)&OlS[(r0 + ri) * STR + c0] = make_float4(a * inv, b * inv, c2 * inv, d2 * inv);
        }
    }
    __syncthreads();

    // out = OS/rsum + Ol @ Wl^T + bl
    {
        ull a01[4], a23[4];
#pragma unroll
        for (int i = 0; i < 4; i++) { a01[i] = 0ull; a23[i] = 0ull; }
#pragma unroll 4
        for (int d = 0; d < 64; d++) {
            ulonglong2 ww = *(const ulonglong2*)&Wlt[d * STR + c0];
            const float* orow = &OlS[d];
            ull w;
            w = splat2(orow[(r0 + 0) * STR]); a01[0] = fma2(w, ww.x, a01[0]); a23[0] = fma2(w, ww.y, a23[0]);
            w = splat2(orow[(r0 + 1) * STR]); a01[1] = fma2(w, ww.x, a01[1]); a23[1] = fma2(w, ww.y, a23[1]);
            w = splat2(orow[(r0 + 2) * STR]); a01[2] = fma2(w, ww.x, a01[2]); a23[2] = fma2(w, ww.y, a23[2]);
            w = splat2(orow[(r0 + 3) * STR]); a01[3] = fma2(w, ww.x, a01[3]); a23[3] = fma2(w, ww.y, a23[3]);
        }
        float4 bv = *(const float4*)&bl[c0];
#pragma unroll
        for (int ri = 0; ri < 4; ri++) {
            float a, b, c2, d2; upk2(a01[ri], a, b); upk2(a23[ri], c2, d2);
            float invr = rsum[r0 + ri];
            float4 osv = *(const float4*)&OS[(r0 + ri) * STR + c0];
            *(float4*)&out[qbase + (size_t)(r0 + ri) * 64 + c0] =
                make_float4(a + bv.x + osv.x * invr, b + bv.y + osv.y * invr,
                            c2 + bv.z + osv.z * invr, d2 + bv.w + osv.w * invr);
        }
    }
}

// ================= launcher =================
extern "C" void kernel_launch(void* const* d_in, const int* in_sizes, int n_in,
                              void* d_out, int out_size) {
    const float* q  = (const float*)d_in[0];
    const float* k  = (const float*)d_in[1];
    const float* v  = (const float*)d_in[2];
    const float* Wl = (const float*)d_in[3];
    const float* bl = (const float*)d_in[4];
    float* out = (float*)d_out;

    const int union_bytes = 5 * 64 * STR * 4 + 256;           // 87,296 (>= mainloop 69,632)
    const int smem_bytes  = 2 * 64 * PSTR * 4 + union_bytes;  // 105,728
    cudaFuncSetAttribute(attn_kernel, cudaFuncAttributeMaxDynamicSharedMemorySize, smem_bytes);

    kvpool_kernel<<<BH * NBLK, 256>>>(q, k, v);
    topk_kernel<<<BH * NBLK, 64>>>();
    total_kernel<<<dim3(BH, 16), 256>>>();
    attn_kernel<<<BH * NBLK, 256, smem_bytes>>>(q, k, v, Wl, bl, out);
}

// round 17
// speedup vs baseline: 1.3210x; 1.0598x over previous
#include <cuda_runtime.h>
#include <cuda_bf16.h>
#include <cstdint>

#define BH    32
#define LSEQ  4096
#define DDIM  64
#define NBLK  64
#define TK    6
#define STR   68          // shared stride (floats), float4-aligned
#define PSTR  36          // bf16x2 pair-row stride in u32 (conflict-free frags)
#define ATT_SCALE 0.125f

typedef unsigned long long ull;
typedef unsigned int u32;

// ---------------- f32x2 packed helpers ----------------
__device__ __forceinline__ ull fma2(ull a, ull b, ull c) {
    ull d; asm("fma.rn.f32x2 %0,%1,%2,%3;" : "=l"(d) : "l"(a), "l"(b), "l"(c)); return d;
}
__device__ __forceinline__ ull splat2(float a) {
    ull r; asm("mov.b64 %0,{%1,%1};" : "=l"(r) : "f"(a)); return r;
}
__device__ __forceinline__ void upk2(ull x, float& a, float& b) {
    asm("mov.b64 {%0,%1},%2;" : "=f"(a), "=f"(b) : "l"(x));
}

// ---------------- bf16 split helpers ----------------
__device__ __forceinline__ u32 packbf(float e, float o) {
    u32 r; asm("cvt.rn.bf16x2.f32 %0,%1,%2;" : "=r"(r) : "f"(o), "f"(e)); return r;
}
__device__ __forceinline__ float lo_f(u32 u) { return __uint_as_float(u << 16); }
__device__ __forceinline__ float hi_f(u32 u) { return __uint_as_float(u & 0xffff0000u); }
__device__ __forceinline__ void split2(float f0, float f1, u32& h, u32& l) {
    h = packbf(f0, f1);
    l = packbf(f0 - lo_f(h), f1 - hi_f(h));
}

// ---------------- mma.sync m16n8k16 bf16 ----------------
__device__ __forceinline__ void mma16816(float* c, const u32* a, const u32* b) {
    asm("mma.sync.aligned.m16n8k16.row.col.f32.bf16.bf16.f32 "
        "{%0,%1,%2,%3},{%4,%5,%6,%7},{%8,%9},{%0,%1,%2,%3};"
        : "+f"(c[0]), "+f"(c[1]), "+f"(c[2]), "+f"(c[3])
        : "r"(a[0]), "r"(a[1]), "r"(a[2]), "r"(a[3]), "r"(b[0]), "r"(b[1]));
}

// ---------------- cp.async helpers ----------------
__device__ __forceinline__ void cp16(u32 saddr, const void* g) {
    asm volatile("cp.async.cg.shared.global [%0], [%1], 16;" :: "r"(saddr), "l"(g));
}
__device__ __forceinline__ void cp_commit() { asm volatile("cp.async.commit_group;"); }
__device__ __forceinline__ void cp_wait0()  { asm volatile("cp.async.wait_group 0;" ::: "memory"); }

// ---------------- device scratch ----------------
__device__ float g_qmean[BH * NBLK * DDIM];
__device__ float g_kmean[BH * NBLK * DDIM];
__device__ int   g_lut[BH * NBLK * TK];
__device__ float g_kv[(size_t)BH * NBLK * DDIM * DDIM];
__device__ float g_z[BH * NBLK * DDIM];
__device__ float g_kvtot[BH * DDIM * DDIM];
__device__ float g_ztot[BH * DDIM];

// ================= K1: fused mean-pool + per-block kv/z (R15 version) =================
__global__ void __launch_bounds__(256) kvpool_kernel(
    const float* __restrict__ q, const float* __restrict__ k, const float* __restrict__ v)
{
    __shared__ __align__(16) float Ks[64 * STR];
    __shared__ __align__(16) float Vs[64 * STR];
    __shared__ float part[8 * 64];   // [0..3]: k-mean partials, [4..7]: q-mean partials
    const int tid = threadIdx.x;
    const size_t base = (size_t)blockIdx.x * 4096;

    for (int i4 = tid; i4 < 1024; i4 += 256) {
        int c = i4 >> 4, e = (i4 & 15) * 4;
        *(float4*)&Ks[c * STR + e] = *(const float4*)&k[base + c * 64 + e];
        *(float4*)&Vs[c * STR + e] = *(const float4*)&v[base + c * 64 + e];
    }
    {
        const int d = tid & 63, mg = tid >> 6;
        const float* qp = q + base + (size_t)mg * 16 * 64 + d;
        float sq = 0.f;
#pragma unroll
        for (int i = 0; i < 16; i++) sq += qp[i * 64];
        part[(4 + mg) * 64 + d] = sq;
    }
    __syncthreads();
    {
        const int d = tid & 63, mg = tid >> 6;
        float sk = 0.f;
#pragma unroll
        for (int i = 0; i < 16; i++) sk += Ks[(mg * 16 + i) * STR + d];
        part[mg * 64 + d] = sk;
    }
    __syncthreads();   // orders mean READS of Ks before softmax WRITES (load-bearing)
    if (tid < 128) {
        const int d = tid & 63, which = tid >> 6;   // 0: k-mean, 1: q-mean
        float s = part[(which * 4 + 0) * 64 + d] + part[(which * 4 + 1) * 64 + d]
                + part[(which * 4 + 2) * 64 + d] + part[(which * 4 + 3) * 64 + d];
        (which ? g_qmean : g_kmean)[blockIdx.x * 64 + d] = s * (1.f / 64.f);
    }
    const int quad = tid >> 2, qd = tid & 3;
    {
        float* row = &Ks[quad * STR + qd * 16];
        float mx = -1e30f;
#pragma unroll
        for (int i = 0; i < 16; i++) mx = fmaxf(mx, row[i]);
        mx = fmaxf(mx, __shfl_xor_sync(0xffffffffu, mx, 1));
        mx = fmaxf(mx, __shfl_xor_sync(0xffffffffu, mx, 2));
        float s = 0.f;
#pragma unroll
        for (int i = 0; i < 16; i++) { float e = __expf(row[i] - mx); row[i] = e; s += e; }
        s += __shfl_xor_sync(0xffffffffu, s, 1);
        s += __shfl_xor_sync(0xffffffffu, s, 2);
        float inv = 1.f / s;
#pragma unroll
        for (int i = 0; i < 16; i++) row[i] *= inv;
    }
    __syncthreads();
    {
        float s = 0.f;
#pragma unroll
        for (int i = 0; i < 16; i++) s += Ks[(qd * 16 + i) * STR + quad];
        s += __shfl_xor_sync(0xffffffffu, s, 1);
        s += __shfl_xor_sync(0xffffffffu, s, 2);
        if (qd == 0) g_z[(size_t)blockIdx.x * 64 + quad] = s;
    }
    const int d = tid & 63;
    const int e0 = (tid >> 6) * 16;
    ull acc[8];
#pragma unroll
    for (int i = 0; i < 8; i++) acc[i] = 0ull;
#pragma unroll 4
    for (int m = 0; m < 64; m++) {
        ull cc = splat2(Ks[m * STR + d]);
        const ulonglong2* vp = (const ulonglong2*)&Vs[m * STR + e0];
#pragma unroll
        for (int t = 0; t < 4; t++) {
            ulonglong2 vv = vp[t];
            acc[2 * t]     = fma2(cc, vv.x, acc[2 * t]);
            acc[2 * t + 1] = fma2(cc, vv.y, acc[2 * t + 1]);
        }
    }
    float* op = &g_kv[(size_t)blockIdx.x * 4096 + d * 64 + e0];
#pragma unroll
    for (int u = 0; u < 4; u++) {
        float4 f;
        upk2(acc[2 * u], f.x, f.y);
        upk2(acc[2 * u + 1], f.z, f.w);
        *(float4*)&op[4 * u] = f;
    }
}

// ================= K2: block scores + top-6 =================
// 8 query blocks per CTA, ONE PER WARP (8 warps = 256 threads; mapping matches launch).
// grid BH*8. Selection logic identical to the R13 baseline.
__global__ void __launch_bounds__(256) topk_kernel() {
    __shared__ __align__(16) float km[64 * STR];
    __shared__ float qv8[8 * 64];
    const int bh = blockIdx.x >> 3, qg = blockIdx.x & 7;
    const int tid = threadIdx.x;
    const int wid = tid >> 5, lane = tid & 31;
    for (int i4 = tid; i4 < 1024; i4 += 256) {
        int c = i4 >> 4, e = (i4 & 15) * 4;
        *(float4*)&km[c * STR + e] = *(const float4*)&g_kmean[bh * 4096 + c * 64 + e];
    }
    for (int i = tid; i < 512; i += 256)
        qv8[i] = g_qmean[bh * 4096 + qg * 512 + i];   // query blocks qg*8..qg*8+7, contiguous
    __syncthreads();

    // warp wid scores query block qi = qg*8+wid; lane owns key blocks lane and lane+32
    float s0 = 0.f, s1 = 0.f;
    const float* qq = &qv8[wid * 64];
#pragma unroll
    for (int dd = 0; dd < 64; dd++) {
        int d0 = (dd + lane) & 63;
        float qv_ = qq[d0];
        s0 += qv_ * km[lane * STR + d0];
        s1 += qv_ * km[(lane + 32) * STR + d0];
    }
    int* lp = &g_lut[(bh * 64 + qg * 8 + wid) * TK];
#pragma unroll
    for (int t = 0; t < TK; t++) {
        float m = (s1 > s0) ? s1 : s0;
        int idx = (s1 > s0) ? (lane + 32) : lane;
#pragma unroll
        for (int off = 16; off; off >>= 1) {
            float om = __shfl_xor_sync(0xffffffffu, m, off);
            int oi = __shfl_xor_sync(0xffffffffu, idx, off);
            if (om > m || (om == m && oi < idx)) { m = om; idx = oi; }
        }
        if (lane == 0) lp[t] = idx;
        if (idx == lane) s0 = -1e38f;
        if (idx == lane + 32) s1 = -1e38f;
    }
}

// ================= K3: totals over key blocks (unchanged) =================
__global__ void total_kernel() {
    const int bh = blockIdx.x;
    const int o = blockIdx.y * 256 + threadIdx.x;
    const float* p = &g_kv[(size_t)bh * NBLK * 4096 + o];
    float s = 0.f;
#pragma unroll 8
    for (int b = 0; b < NBLK; b++) s += p[(size_t)b * 4096];
    g_kvtot[bh * 4096 + o] = s;
    if (blockIdx.y == 0 && threadIdx.x < 64) {
        float z = 0.f;
#pragma unroll
        for (int b = 0; b < NBLK; b++) z += g_z[((size_t)bh * NBLK + b) * 64 + threadIdx.x];
        g_ztot[bh * 64 + threadIdx.x] = z;
    }
}

// ================= K4: attn (R14, byte-identical) =================
__global__ void __launch_bounds__(256, 2) attn_kernel(
    const float* __restrict__ q, const float* __restrict__ k, const float* __restrict__ v,
    const float* __restrict__ Wl, const float* __restrict__ bl, float* __restrict__ out)
{
    extern __shared__ __align__(16) unsigned char smraw[];
    u32* Qh = (u32*)smraw;
    u32* Ql = Qh + 64 * PSTR;
    unsigned char* U = (unsigned char*)(Ql + 64 * PSTR);
    u32* Kh = (u32*)U;
    u32* Kl = Kh + 64 * PSTR;
    u32* Vh = Kl + 64 * PSTR;
    u32* Vl = Vh + 64 * PSTR;
    float* Kraw = (float*)(Vl + 64 * PSTR);
    float* Vraw = Kraw + 4096;
    float* OS   = (float*)U;
    float* PhiT = OS   + 64 * STR;
    float* KVns = PhiT + 64 * STR;
    float* OlS  = KVns + 64 * STR;
    float* Wlt  = OlS  + 64 * STR;
    float* zns  = Wlt  + 64 * STR;
    __shared__ float rsum[64];

    const int tid  = threadIdx.x;
    const int lane = tid & 31;
    const int wid  = tid >> 5;
    const int R    = (wid & 3) * 16;
    const int wcol = wid >> 2;
    const int g    = lane >> 2, t = lane & 3;
    const int bh = blockIdx.x >> 6, qi = blockIdx.x & 63;
    const size_t qbase = ((size_t)bh * LSEQ + qi * 64) * DDIM;

    int lutr[TK];
#pragma unroll
    for (int j = 0; j < TK; j++) lutr[j] = g_lut[(bh * 64 + qi) * TK + j];

    const u32 kraw_s = (u32)__cvta_generic_to_shared(Kraw);
    const u32 vraw_s = (u32)__cvta_generic_to_shared(Vraw);

    {
        const size_t kb = ((size_t)bh * LSEQ + lutr[0] * 64) * DDIM;
#pragma unroll
        for (int i = 0; i < 4; i++) {
            int o = (tid + 256 * i) * 4;
            cp16(kraw_s + o * 4, k + kb + o);
            cp16(vraw_s + o * 4, v + kb + o);
        }
        cp_commit();
    }

#pragma unroll
    for (int i = 0; i < 8; i++) {
        int id = tid + 256 * i;
        int c = id >> 5, p = id & 31;
        float2 f = *(const float2*)&q[qbase + c * 64 + 2 * p];
        u32 h, l; split2(f.x, f.y, h, l);
        Qh[c * PSTR + p] = h; Ql[c * PSTR + p] = l;
    }

    float O[8][4];
#pragma unroll
    for (int i = 0; i < 8; i++) { O[i][0] = O[i][1] = O[i][2] = O[i][3] = 0.f; }
    float rs0 = 0.f, rs1 = 0.f;

    for (int j = 0; j < TK; j++) {
        cp_wait0();
        __syncthreads();
#pragma unroll
        for (int i = 0; i < 8; i++) {
            int id = tid + 256 * i;
            int c = id >> 5, p = id & 31;
            float2 f = *(const float2*)&Kraw[c * 64 + 2 * p];
            u32 h, l; split2(f.x, f.y, h, l);
            Kh[c * PSTR + p] = h; Kl[c * PSTR + p] = l;
        }
#pragma unroll
        for (int i = 0; i < 8; i++) {
            int id = tid + 256 * i;
            int e = id & 63, pp = id >> 6;
            float a = Vraw[(2 * pp) * 64 + e];
            float b = Vraw[(2 * pp + 1) * 64 + e];
            u32 h, l; split2(a, b, h, l);
            int psw = pp ^ ((e >> 3) & 3);
            Vh[e * PSTR + psw] = h; Vl[e * PSTR + psw] = l;
        }
        __syncthreads();
        if (j + 1 < TK) {
            const size_t kb = ((size_t)bh * LSEQ + lutr[j + 1] * 64) * DDIM;
#pragma unroll
            for (int i = 0; i < 4; i++) {
                int o = (tid + 256 * i) * 4;
                cp16(kraw_s + o * 4, k + kb + o);
                cp16(vraw_s + o * 4, v + kb + o);
            }
            cp_commit();
        }

        float S[4][4];
#pragma unroll
        for (int i = 0; i < 4; i++) { S[i][0] = S[i][1] = S[i][2] = S[i][3] = 0.f; }
        const int ao0 = (R + g) * PSTR + t, ao1 = (R + g + 8) * PSTR + t;
#pragma unroll
        for (int s = 0; s < 4; s++) {
            u32 ah[4], al[4];
            ah[0] = Qh[ao0 + s * 8];     ah[1] = Qh[ao1 + s * 8];
            ah[2] = Qh[ao0 + s * 8 + 4]; ah[3] = Qh[ao1 + s * 8 + 4];
            al[0] = Ql[ao0 + s * 8];     al[1] = Ql[ao1 + s * 8];
            al[2] = Ql[ao0 + s * 8 + 4]; al[3] = Ql[ao1 + s * 8 + 4];
#pragma unroll
            for (int nt = 0; nt < 4; nt++) {
                int bo = ((wcol * 4 + nt) * 8 + g) * PSTR + s * 8 + t;
                u32 bhv[2] = { Kh[bo], Kh[bo + 4] };
                u32 blv[2] = { Kl[bo], Kl[bo + 4] };
                mma16816(S[nt], ah, bhv);
                mma16816(S[nt], ah, blv);
                mma16816(S[nt], al, bhv);
            }
        }
        u32 ph01[4], ph23[4], pl01[4], pl23[4];
#pragma unroll
        for (int nt = 0; nt < 4; nt++) {
            float p0 = __expf(S[nt][0] * ATT_SCALE);
            float p1 = __expf(S[nt][1] * ATT_SCALE);
            float p2 = __expf(S[nt][2] * ATT_SCALE);
            float p3 = __expf(S[nt][3] * ATT_SCALE);
            rs0 += p0 + p1; rs1 += p2 + p3;
            split2(p0, p1, ph01[nt], pl01[nt]);
            split2(p2, p3, ph23[nt], pl23[nt]);
        }
#pragma unroll
        for (int s = 0; s < 2; s++) {
            u32 ah[4] = { ph01[2 * s], ph23[2 * s], ph01[2 * s + 1], ph23[2 * s + 1] };
            u32 al[4] = { pl01[2 * s], pl23[2 * s], pl01[2 * s + 1], pl23[2 * s + 1] };
#pragma unroll
            for (int et = 0; et < 8; et++) {
                int x = et & 3;
                int bo = (et * 8 + g) * PSTR + wcol * 16 + s * 8 + (t ^ x);
                u32 bhv[2] = { Vh[bo], Vh[bo + 4] };
                u32 blv[2] = { Vl[bo], Vl[bo + 4] };
                mma16816(O[et], ah, bhv);
                mma16816(O[et], ah, blv);
                mma16816(O[et], al, bhv);
            }
        }
    }
    __syncthreads();

    rs0 += __shfl_xor_sync(0xffffffffu, rs0, 1); rs0 += __shfl_xor_sync(0xffffffffu, rs0, 2);
    rs1 += __shfl_xor_sync(0xffffffffu, rs1, 1); rs1 += __shfl_xor_sync(0xffffffffu, rs1, 2);

    if (wcol == 0) {
        if (t == 0) { rsum[R + g] = rs0; rsum[R + g + 8] = rs1; }
#pragma unroll
        for (int et = 0; et < 8; et++) {
            int c = et * 8 + 2 * t;
            OS[(R + g) * STR + c]         = O[et][0];
            OS[(R + g) * STR + c + 1]     = O[et][1];
            OS[(R + g + 8) * STR + c]     = O[et][2];
            OS[(R + g + 8) * STR + c + 1] = O[et][3];
        }
    }
    __syncthreads();
    if (wcol == 1) {
        if (t == 0) { rsum[R + g] += rs0; rsum[R + g + 8] += rs1; }
#pragma unroll
        for (int et = 0; et < 8; et++) {
            int c = et * 8 + 2 * t;
            OS[(R + g) * STR + c]         += O[et][0];
            OS[(R + g) * STR + c + 1]     += O[et][1];
            OS[(R + g + 8) * STR + c]     += O[et][2];
            OS[(R + g + 8) * STR + c + 1] += O[et][3];
        }
    }
    __syncthreads();

    for (int i = tid; i < 4096; i += 256) {
        int a = i >> 6, b = i & 63;
        Wlt[b * STR + a] = Wl[i];
    }
    {
        const float* kvt = &g_kvtot[bh * 4096];
        const float* kvb = &g_kv[(size_t)bh * NBLK * 4096];
        const int o0 = tid * 16;
#pragma unroll
        for (int u = 0; u < 4; u++) {
            int o = o0 + 4 * u;
            float4 a = *(const float4*)&kvt[o];
#pragma unroll
            for (int j = 0; j < TK; j++) {
                float4 b4 = *(const float4*)&kvb[(size_t)lutr[j] * 4096 + o];
                a.x -= b4.x; a.y -= b4.y; a.z -= b4.z; a.w -= b4.w;
            }
            *(float4*)&KVns[(o >> 6) * STR + (o & 63)] = a;
        }
    }
    if (tid < 64) {
        const int r = tid;
        float mx = -1e30f;
#pragma unroll
        for (int p = 0; p < 32; p++) {
            u32 h = Qh[r * PSTR + p], l = Ql[r * PSTR + p];
            float e0 = lo_f(h) + lo_f(l), e1 = hi_f(h) + hi_f(l);
            mx = fmaxf(mx, fmaxf(e0, e1));
        }
        float s = 0.f;
#pragma unroll
        for (int p = 0; p < 32; p++) {
            u32 h = Qh[r * PSTR + p], l = Ql[r * PSTR + p];
            float e0 = __expf(lo_f(h) + lo_f(l) - mx);
            float e1 = __expf(hi_f(h) + hi_f(l) - mx);
            PhiT[(2 * p) * STR + r] = e0; PhiT[(2 * p + 1) * STR + r] = e1;
            s += e0 + e1;
        }
        float inv = 1.f / s;
#pragma unroll
        for (int d = 0; d < 64; d++) PhiT[d * STR + r] *= inv;
    } else if (tid < 128) {
        const int r = tid - 64;
        float zz = g_ztot[bh * 64 + r];
#pragma unroll
        for (int j = 0; j < TK; j++) zz -= g_z[((size_t)bh * NBLK + lutr[j]) * 64 + r];
        zns[r] = zz;
    } else if (tid < 192) {
        const int r = tid - 128;
        rsum[r] = 1.f / rsum[r];
    }
    __syncthreads();

    const int tr = tid >> 4, tc = tid & 15;
    const int r0 = tr * 4, c0 = tc * 4;

    {
        ull n01[4], n23[4]; float den[4];
#pragma unroll
        for (int i = 0; i < 4; i++) { n01[i] = 0ull; n23[i] = 0ull; den[i] = 0.f; }
#pragma unroll 8
        for (int d = 0; d < 64; d++) {
            float4 qa = *(const float4*)&PhiT[d * STR + r0];
            ulonglong2 kk = *(const ulonglong2*)&KVns[d * STR + c0];
            float zd = zns[d];
            ull w;
            w = splat2(qa.x); n01[0] = fma2(w, kk.x, n01[0]); n23[0] = fma2(w, kk.y, n23[0]); den[0] = fmaf(qa.x, zd, den[0]);
            w = splat2(qa.y); n01[1] = fma2(w, kk.x, n01[1]); n23[1] = fma2(w, kk.y, n23[1]); den[1] = fmaf(qa.y, zd, den[1]);
            w = splat2(qa.z); n01[2] = fma2(w, kk.x, n01[2]); n23[2] = fma2(w, kk.y, n23[2]); den[2] = fmaf(qa.z, zd, den[2]);
            w = splat2(qa.w); n01[3] = fma2(w, kk.x, n01[3]); n23[3] = fma2(w, kk.y, n23[3]); den[3] = fmaf(qa.w, zd, den[3]);
        }
#pragma unroll
        for (int ri = 0; ri < 4; ri++) {
            float inv = 1.f / (den[ri] + 1e-6f);
            float a, b, c2, d2; upk2(n01[ri], a, b); upk2(n23[ri], c2, d2);
            *(float4*)&OlS[(r0 + ri) * STR + c0] = make_float4(a * inv, b * inv, c2 * inv, d2 * inv);
        }
    }
    __syncthreads();

    {
        ull a01[4], a23[4];
#pragma unroll
        for (int i = 0; i < 4; i++) { a01[i] = 0ull; a23[i] = 0ull; }
#pragma unroll 4
        for (int d = 0; d < 64; d++) {
            ulonglong2 ww = *(const ulonglong2*)&Wlt[d * STR + c0];
            const float* orow = &OlS[d];
            ull w;
            w = splat2(orow[(r0 + 0) * STR]); a01[0] = fma2(w, ww.x, a01[0]); a23[0] = fma2(w, ww.y, a23[0]);
            w = splat2(orow[(r0 + 1) * STR]); a01[1] = fma2(w, ww.x, a01[1]); a23[1] = fma2(w, ww.y, a23[1]);
            w = splat2(orow[(r0 + 2) * STR]); a01[2] = fma2(w, ww.x, a01[2]); a23[2] = fma2(w, ww.y, a23[2]);
            w = splat2(orow[(r0 + 3) * STR]); a01[3] = fma2(w, ww.x, a01[3]); a23[3] = fma2(w, ww.y, a23[3]);
        }
        float4 bv = *(const float4*)&bl[c0];
#pragma unroll
        for (int ri = 0; ri < 4; ri++) {
            float a, b, c2, d2; upk2(a01[ri], a, b); upk2(a23[ri], c2, d2);
            float invr = rsum[r0 + ri];
            float4 osv = *(const float4*)&OS[(r0 + ri) * STR + c0];
            *(float4*)&out[qbase + (size_t)(r0 + ri) * 64 + c0] =
                make_float4(a + bv.x + osv.x * invr, b + bv.y + osv.y * invr,
                            c2 + bv.z + osv.z * invr, d2 + bv.w + osv.w * invr);
        }
    }
}

// ================= launcher =================
extern "C" void kernel_launch(void* const* d_in, const int* in_sizes, int n_in,
                              void* d_out, int out_size) {
    const float* q  = (const float*)d_in[0];
    const float* k  = (const float*)d_in[1];
    const float* v  = (const float*)d_in[2];
    const float* Wl = (const float*)d_in[3];
    const float* bl = (const float*)d_in[4];
    float* out = (float*)d_out;

    const int union_bytes = 5 * 64 * STR * 4 + 256;           // 87,296
    const int smem_bytes  = 2 * 64 * PSTR * 4 + union_bytes;  // 105,728
    cudaFuncSetAttribute(attn_kernel, cudaFuncAttributeMaxDynamicSharedMemorySize, smem_bytes);

    kvpool_kernel<<<BH * NBLK, 256>>>(q, k, v);
    topk_kernel<<<BH * 8, 256>>>();
    total_kernel<<<dim3(BH, 16), 256>>>();
    attn_kernel<<<BH * NBLK, 256, smem_bytes>>>(q, k, v, Wl, bl, out);
}